// round 14
// baseline (speedup 1.0000x reference)
#include <cuda_runtime.h>
#include <cuda_fp16.h>
#include <math.h>
#include <stdint.h>

#define Bb    2
#define SEQ   2048
#define Hh    1024
#define NHd   16
#define Dd    64
#define Mtok  4096

__device__ float  g_f32[(size_t)3 * Mtok * Hh];   // reused as half qlin/klin/vlin
__device__ __half g_f16[(size_t)(4 + 4 + 12 + 4) * 1024 * 1024];

__device__ __forceinline__ void cp_async16(void* smem, const void* gmem) {
    unsigned saddr = (unsigned)__cvta_generic_to_shared(smem);
    asm volatile("cp.async.cg.shared.global [%0], [%1], 16;\n" :: "r"(saddr), "l"(gmem));
}
__device__ __forceinline__ void cp_commit() { asm volatile("cp.async.commit_group;\n"); }
template <int N>
__device__ __forceinline__ void cp_wait() { asm volatile("cp.async.wait_group %0;\n" :: "n"(N)); }

__device__ __forceinline__ void ldsm_x4(uint32_t* r, uint32_t saddr) {
    asm volatile("ldmatrix.sync.aligned.m8n8.x4.shared.b16 {%0,%1,%2,%3}, [%4];"
                 : "=r"(r[0]), "=r"(r[1]), "=r"(r[2]), "=r"(r[3]) : "r"(saddr));
}
__device__ __forceinline__ void ldsm_x4_t(uint32_t* r, uint32_t saddr) {
    asm volatile("ldmatrix.sync.aligned.m8n8.x4.trans.shared.b16 {%0,%1,%2,%3}, [%4];"
                 : "=r"(r[0]), "=r"(r[1]), "=r"(r[2]), "=r"(r[3]) : "r"(saddr));
}
__device__ __forceinline__ void mma16816(float* c, const uint32_t* a, const uint32_t* b) {
    asm volatile(
        "mma.sync.aligned.m16n8k16.row.col.f32.f16.f16.f32 "
        "{%0,%1,%2,%3}, {%4,%5,%6,%7}, {%8,%9}, {%0,%1,%2,%3};"
        : "+f"(c[0]), "+f"(c[1]), "+f"(c[2]), "+f"(c[3])
        : "r"(a[0]), "r"(a[1]), "r"(a[2]), "r"(a[3]), "r"(b[0]), "r"(b[1]));
}
__device__ __forceinline__ uint32_t packh2(float x, float y) {
    __half2 h = __floats2half2_rn(x, y);
    return *(uint32_t*)&h;
}
__device__ __forceinline__ float ex2f(float x) {
    float y; asm("ex2.approx.f32 %0, %1;" : "=f"(y) : "f"(x)); return y;
}

// ---------------------------------------------------------------------------
// fused fp32->fp16 conversion
// ---------------------------------------------------------------------------
#define SZc ((size_t)Mtok * Hh)
#define WZc ((size_t)Hh * Hh)
__global__ __launch_bounds__(256)
void f2h_all_kernel(const float* __restrict__ hs,
                    const float* __restrict__ Wq, const float* __restrict__ Wk,
                    const float* __restrict__ Wv, const float* __restrict__ Wo,
                    __half* __restrict__ dst)
{
    size_t i4 = ((size_t)blockIdx.x * 256 + threadIdx.x) * 4;
    const float* s;
    if (i4 < SZc) s = &hs[i4];
    else {
        size_t wo = i4 - SZc;
        s = (wo < WZc)     ? &Wq[wo]
          : (wo < 2 * WZc) ? &Wk[wo - WZc]
          : (wo < 3 * WZc) ? &Wv[wo - 2 * WZc]
                           : &Wo[wo - 3 * WZc];
    }
    float4 v = *(const float4*)s;
    *(__half2*)&dst[i4]     = __floats2half2_rn(v.x, v.y);
    *(__half2*)&dst[i4 + 2] = __floats2half2_rn(v.z, v.w);
}

// ---------------------------------------------------------------------------
// Raw-mma fp16 GEMM: C[M,N] = A[M,K] @ W[N,K]^T.
// 128x128 CTA tile, 8 warps x (32x64), BK=64, 3-stage cp.async (wait<1>),
// 16 iterations => half the barriers of the BK=32 version.
// Register epilogue (half2 or float2+bias stores).
// ---------------------------------------------------------------------------
#define GBK  64
#define GLDG 72                          // halfs per smem row (144 B)
#define GSTG (128 * GLDG)                // halfs per A (or B) stage
#define GNS  3
#define GEMM_SMEM (2 * GNS * GSTG * 2)   // 3 stages x (A+B) x 2B = 110592
#define NITER 16

__global__ __launch_bounds__(256, 2)
void gemm_mma_kernel(const __half* __restrict__ A,
                     const __half* __restrict__ W0, const __half* __restrict__ W1,
                     const __half* __restrict__ W2,
                     __half* __restrict__ H0, __half* __restrict__ H1,
                     __half* __restrict__ H2,
                     float* __restrict__ F, const float* __restrict__ bias)
{
    extern __shared__ __align__(16) __half gsm[];
    __half* As = gsm;                    // [3][GSTG]
    __half* Bs = gsm + GNS * GSTG;       // [3][GSTG]

    const __half* W = (blockIdx.z == 0) ? W0 : (blockIdx.z == 1) ? W1 : W2;
    __half*       H = (blockIdx.z == 0) ? H0 : (blockIdx.z == 1) ? H1 : H2;

    const int tid  = threadIdx.x;
    const int w    = tid >> 5;
    const int lane = tid & 31;
    const int wr = w & 3;
    const int wc = w >> 2;
    const int bm = blockIdx.y * 128, bn = blockIdx.x * 128;
    const int K = 1024;

    float acc[2][8][4];
    #pragma unroll
    for (int m = 0; m < 2; m++)
        #pragma unroll
        for (int n = 0; n < 8; n++)
            #pragma unroll
            for (int j = 0; j < 4; j++) acc[m][n][j] = 0.f;

    // loaders: each thread covers 1 row slot (2 threads/row), 4 cp16 per matrix
    const int lr = tid >> 1;             // 0..127
    const int lc = (tid & 1) * 32;       // half-col base

    // prefetch stages 0,1
    #pragma unroll
    for (int st = 0; st < 2; st++) {
        const int k0 = st * GBK;
        #pragma unroll
        for (int i = 0; i < 4; i++) {
            int c8 = lc + i * 8;
            cp_async16(&As[st * GSTG + lr * GLDG + c8], &A[(size_t)(bm + lr) * K + k0 + c8]);
            cp_async16(&Bs[st * GSTG + lr * GLDG + c8], &W[(size_t)(bn + lr) * K + k0 + c8]);
        }
        cp_commit();
    }

    const uint32_t as_b = (uint32_t)__cvta_generic_to_shared(As);
    const uint32_t bs_b = (uint32_t)__cvta_generic_to_shared(Bs);

    const int aA_row = wr * 32 + (lane & 15);
    const int aA_col = 8 * (lane >> 4);
    const int bB_row = wc * 64 + (lane & 7) + 8 * (lane >> 4);
    const int bB_col = 8 * ((lane >> 3) & 1);

    int sidx = 0;
    for (int it = 0; it < NITER; it++) {
        if (it < NITER - 1) cp_wait<1>(); else cp_wait<0>();
        __syncthreads();

        if (it + 2 < NITER) {
            const int st = (sidx + 2 >= 3) ? sidx - 1 : sidx + 2;
            const int k0 = (it + 2) * GBK;
            #pragma unroll
            for (int i = 0; i < 4; i++) {
                int c8 = lc + i * 8;
                cp_async16(&As[st * GSTG + lr * GLDG + c8], &A[(size_t)(bm + lr) * K + k0 + c8]);
                cp_async16(&Bs[st * GSTG + lr * GLDG + c8], &W[(size_t)(bn + lr) * K + k0 + c8]);
            }
            cp_commit();
        }

        const uint32_t as_s = as_b + (uint32_t)(sidx * GSTG) * 2;
        const uint32_t bs_s = bs_b + (uint32_t)(sidx * GSTG) * 2;

        #pragma unroll
        for (int kk = 0; kk < 4; kk++) {        // 4 x K=16 per BK=64 tile
            const int kd = kk * 16;
            uint32_t af[2][4];
            #pragma unroll
            for (int m = 0; m < 2; m++)
                ldsm_x4(af[m], as_s + (uint32_t)((aA_row + m * 16) * GLDG + kd + aA_col) * 2);
            #pragma unroll
            for (int np = 0; np < 4; np++) {
                uint32_t bf[4];
                ldsm_x4(bf, bs_s + (uint32_t)((bB_row + np * 16) * GLDG + kd + bB_col) * 2);
                mma16816(acc[0][np * 2],     af[0], bf);
                mma16816(acc[0][np * 2 + 1], af[0], bf + 2);
                mma16816(acc[1][np * 2],     af[1], bf);
                mma16816(acc[1][np * 2 + 1], af[1], bf + 2);
            }
        }
        sidx = (sidx + 1 >= 3) ? 0 : sidx + 1;
    }

    const int colb = 2 * (lane & 3);
    if (H != nullptr) {
        #pragma unroll
        for (int m = 0; m < 2; m++) {
            const int r0 = bm + wr * 32 + m * 16 + (lane >> 2);
            __half* p0 = &H[(size_t)r0 * 1024 + bn + wc * 64];
            __half* p1 = &H[(size_t)(r0 + 8) * 1024 + bn + wc * 64];
            #pragma unroll
            for (int n = 0; n < 8; n++) {
                *(uint32_t*)&p0[n * 8 + colb] = packh2(acc[m][n][0], acc[m][n][1]);
                *(uint32_t*)&p1[n * 8 + colb] = packh2(acc[m][n][2], acc[m][n][3]);
            }
        }
    } else {
        #pragma unroll
        for (int m = 0; m < 2; m++) {
            const int r0 = bm + wr * 32 + m * 16 + (lane >> 2);
            float* p0 = &F[(size_t)r0 * 1024 + bn + wc * 64];
            float* p1 = &F[(size_t)(r0 + 8) * 1024 + bn + wc * 64];
            const float* bp = &bias[bn + wc * 64];
            #pragma unroll
            for (int n = 0; n < 8; n++) {
                float b0 = bp[n * 8 + colb], b1 = bp[n * 8 + colb + 1];
                float2 o0 = { acc[m][n][0] + b0, acc[m][n][1] + b1 };
                float2 o1 = { acc[m][n][2] + b0, acc[m][n][3] + b1 };
                *(float2*)&p0[n * 8 + colb] = o0;
                *(float2*)&p1[n * 8 + colb] = o1;
            }
        }
    }
}

// ---------------------------------------------------------------------------
// RMSNorm + bias + RoPE (vectorized). Outputs half q/k/v in [B,NH,S,D];
// q pre-scaled by 0.125*log2(e).
// ---------------------------------------------------------------------------
#define QSCALE (0.125f * 1.44269504089f)

__global__ __launch_bounds__(256)
void normrope_kernel(const __half* __restrict__ qlin, const __half* __restrict__ klin,
                     const __half* __restrict__ vlin,
                     const float* __restrict__ bq, const float* __restrict__ bk,
                     const float* __restrict__ bv,
                     const float* __restrict__ cosT, const float* __restrict__ sinT,
                     const float* __restrict__ w,
                     __half* __restrict__ qo, __half* __restrict__ ko, __half* __restrict__ vo)
{
    const int t = blockIdx.x;
    const int b = t >> 11;
    const int s = t & 2047;
    const int tid = threadIdx.x;
    const int i0 = tid * 4;

    __shared__ float sq[1024], sk[1024];
    __shared__ float red[16];
    __shared__ float rqs, rks;

    float sumq = 0.f, sumk = 0.f;
    {
        __half2 q01 = *(const __half2*)&qlin[(size_t)t * 1024 + i0];
        __half2 q23 = *(const __half2*)&qlin[(size_t)t * 1024 + i0 + 2];
        __half2 k01 = *(const __half2*)&klin[(size_t)t * 1024 + i0];
        __half2 k23 = *(const __half2*)&klin[(size_t)t * 1024 + i0 + 2];
        float4 bq4 = *(const float4*)&bq[i0];
        float4 bk4 = *(const float4*)&bk[i0];
        float x0 = __half2float(q01.x) + bq4.x, x1 = __half2float(q01.y) + bq4.y;
        float x2 = __half2float(q23.x) + bq4.z, x3 = __half2float(q23.y) + bq4.w;
        float y0 = __half2float(k01.x) + bk4.x, y1 = __half2float(k01.y) + bk4.y;
        float y2 = __half2float(k23.x) + bk4.z, y3 = __half2float(k23.y) + bk4.w;
        sq[i0] = x0; sq[i0 + 1] = x1; sq[i0 + 2] = x2; sq[i0 + 3] = x3;
        sk[i0] = y0; sk[i0 + 1] = y1; sk[i0 + 2] = y2; sk[i0 + 3] = y3;
        sumq = (x0 * x0 + x1 * x1) + (x2 * x2 + x3 * x3);
        sumk = (y0 * y0 + y1 * y1) + (y2 * y2 + y3 * y3);
    }
    #pragma unroll
    for (int off = 16; off > 0; off >>= 1) {
        sumq += __shfl_down_sync(0xffffffffu, sumq, off);
        sumk += __shfl_down_sync(0xffffffffu, sumk, off);
    }
    if ((tid & 31) == 0) { red[tid >> 5] = sumq; red[8 + (tid >> 5)] = sumk; }
    __syncthreads();
    if (tid == 0) {
        float a = 0.f, c = 0.f;
        #pragma unroll
        for (int i2 = 0; i2 < 8; i2++) { a += red[i2]; c += red[8 + i2]; }
        rqs = rsqrtf(a * (1.0f / 1024.0f) + 1e-6f);
        rks = rsqrtf(c * (1.0f / 1024.0f) + 1e-6f);
    }
    __syncthreads();
    const float rq = rqs, rk = rks;

    {
        const int h = i0 >> 6, d = i0 & 63;
        const int pbase = (d < 32) ? i0 + 32 : i0 - 32;
        const float sign = (d < 32) ? -1.f : 1.f;
        float4 cs4 = *(const float4*)&cosT[s * 64 + d];
        float4 sn4 = *(const float4*)&sinT[s * 64 + d];
        float4 w4  = *(const float4*)&w[i0];
        float4 wp4 = *(const float4*)&w[pbase];
        float qv[4], kv[4];
        #pragma unroll
        for (int j = 0; j < 4; j++) {
            float wv = (&w4.x)[j], wp = (&wp4.x)[j];
            float cs = (&cs4.x)[j], sn = (&sn4.x)[j];
            float qx = sq[i0 + j] * rq * wv, qp = sq[pbase + j] * rq * wp;
            float kx = sk[i0 + j] * rk * wv, kp = sk[pbase + j] * rk * wp;
            qv[j] = (qx * cs + sign * qp * sn) * QSCALE;
            kv[j] = kx * cs + sign * kp * sn;
        }
        size_t oidx = ((size_t)(b * NHd + h) * SEQ + s) * Dd + d;
        *(__half2*)&qo[oidx]     = __floats2half2_rn(qv[0], qv[1]);
        *(__half2*)&qo[oidx + 2] = __floats2half2_rn(qv[2], qv[3]);
        *(__half2*)&ko[oidx]     = __floats2half2_rn(kv[0], kv[1]);
        *(__half2*)&ko[oidx + 2] = __floats2half2_rn(kv[2], kv[3]);
        __half2 v01 = *(const __half2*)&vlin[(size_t)t * 1024 + i0];
        __half2 v23 = *(const __half2*)&vlin[(size_t)t * 1024 + i0 + 2];
        float4 bv4 = *(const float4*)&bv[i0];
        *(__half2*)&vo[oidx]     = __floats2half2_rn(__half2float(v01.x) + bv4.x,
                                                     __half2float(v01.y) + bv4.y);
        *(__half2*)&vo[oidx + 2] = __floats2half2_rn(__half2float(v23.x) + bv4.z,
                                                     __half2float(v23.y) + bv4.w);
    }
}

// ---------------------------------------------------------------------------
// Flash attention (best measured config): raw mma.sync, 8 warps x 16 q-rows,
// register S/P, exp2-domain scores, 3-stage K/V ring (one barrier per tile),
// softmax interleaved with PV per 16-key chunk.
// ---------------------------------------------------------------------------
#define QLD 72
#define FTILE (64 * QLD)
#define FSM_BYTES ((128 * QLD + 6 * FTILE) * 2)    // 73728
#define C_IN  (-2.88539008178f)
#define C_OUT (-4.32808512267f)

__global__ __launch_bounds__(256, 2)
void flash_mma_kernel(const __half* __restrict__ q, const __half* __restrict__ k,
                      const __half* __restrict__ v, __half* __restrict__ out)
{
    extern __shared__ __align__(16) char smraw[];
    __half* Qs = (__half*)smraw;               // [128][QLD]
    __half* Ks = Qs + 128 * QLD;               // [3][64][QLD]
    __half* Vs = Ks + 3 * FTILE;               // [3][64][QLD]

    const int tid  = threadIdx.x;
    const int w    = tid >> 5;
    const int lane = tid & 31;
    const int bh   = blockIdx.y;
    const int qt   = blockIdx.x;
    const __half* kb = k + (size_t)bh * SEQ * Dd;
    const __half* vb = v + (size_t)bh * SEQ * Dd;
    const __half* qb = q + ((size_t)bh * SEQ + qt * 128) * Dd;

    // stage Q + K/V tiles 0 and 1
    {
        int r = tid >> 1, c0 = (tid & 1) * 32;
        #pragma unroll
        for (int i = 0; i < 4; i++)
            cp_async16(&Qs[r * QLD + c0 + i * 8], &qb[(size_t)r * Dd + c0 + i * 8]);
        int lr = tid >> 2, lc = (tid & 3) * 16;
        #pragma unroll
        for (int st = 0; st < 2; st++) {
            #pragma unroll
            for (int i = 0; i < 2; i++) {
                cp_async16(&Ks[st * FTILE + lr * QLD + lc + i * 8],
                           &kb[(size_t)(st * 64 + lr) * Dd + lc + i * 8]);
                cp_async16(&Vs[st * FTILE + lr * QLD + lc + i * 8],
                           &vb[(size_t)(st * 64 + lr) * Dd + lc + i * 8]);
            }
            cp_commit();
        }
    }

    const uint32_t qs_b = (uint32_t)__cvta_generic_to_shared(Qs);
    const uint32_t ks_b = (uint32_t)__cvta_generic_to_shared(Ks);
    const uint32_t vs_b = (uint32_t)__cvta_generic_to_shared(Vs);

    cp_wait<1>();
    __syncthreads();

    uint32_t qa[4][4];
    {
        int r = w * 16 + (lane & 15);
        int cbase = 8 * (lane >> 4);
        #pragma unroll
        for (int kk = 0; kk < 4; kk++)
            ldsm_x4(qa[kk], qs_b + (uint32_t)(r * QLD + kk * 16 + cbase) * 2);
    }

    float oacc[8][4];
    #pragma unroll
    for (int i = 0; i < 8; i++)
        #pragma unroll
        for (int j = 0; j < 4; j++) oacc[i][j] = 0.f;
    float l0 = 0.f, l1 = 0.f;

    const int colb  = 2 * (lane & 3);
    const int row0g = qt * 128 + w * 16 + (lane >> 2);

    const int kK_row = (lane & 7) + 8 * (lane >> 4);
    const int kK_col = 8 * ((lane >> 3) & 1);
    const int vV_row = (lane & 7) + 8 * ((lane >> 3) & 1);
    const int vV_col = 8 * (lane >> 4);

    const int NT = SEQ / 64;
    int sidx = 0;
    for (int t = 0; t < NT; t++) {
        const int kt = t * 64;
        if (t < NT - 1) cp_wait<1>(); else cp_wait<0>();
        __syncthreads();

        if (t + 2 < NT) {
            const int st = (sidx + 2 >= 3) ? sidx - 1 : sidx + 2;
            const int kn = kt + 128;
            __half* Kd = &Ks[st * FTILE];
            __half* Vd = &Vs[st * FTILE];
            int lr = tid >> 2, lc = (tid & 3) * 16;
            #pragma unroll
            for (int i = 0; i < 2; i++) {
                cp_async16(&Kd[lr * QLD + lc + i * 8], &kb[(size_t)(kn + lr) * Dd + lc + i * 8]);
                cp_async16(&Vd[lr * QLD + lc + i * 8], &vb[(size_t)(kn + lr) * Dd + lc + i * 8]);
            }
            cp_commit();
        }

        const uint32_t ks_s = ks_b + (uint32_t)(sidx * FTILE) * 2;
        const uint32_t vs_s = vs_b + (uint32_t)(sidx * FTILE) * 2;

        // ---- S = Q @ K^T ----
        float sfr[8][4];
        #pragma unroll
        for (int i = 0; i < 8; i++)
            #pragma unroll
            for (int j = 0; j < 4; j++) sfr[i][j] = 0.f;

        #pragma unroll
        for (int kk = 0; kk < 4; kk++) {
            const int d0 = kk * 16;
            #pragma unroll
            for (int np = 0; np < 4; np++) {
                uint32_t kr[4];
                ldsm_x4(kr, ks_s + (uint32_t)((np * 16 + kK_row) * QLD + d0 + kK_col) * 2);
                mma16816(sfr[2 * np],     qa[kk], kr);
                mma16816(sfr[2 * np + 1], qa[kk], kr + 2);
            }
        }

        // ---- per 16-key chunk: softmax -> PV ----
        #pragma unroll
        for (int kk = 0; kk < 4; kk++) {
            uint32_t pa[4];
            #pragma unroll
            for (int half16 = 0; half16 < 2; half16++) {
                const int nt = kk * 2 + half16;
                int col = kt + nt * 8 + colb;
                float p0 = ex2f(sfr[nt][0] + ((col    ) <= row0g     ? C_IN : C_OUT));
                float p1 = ex2f(sfr[nt][1] + ((col + 1) <= row0g     ? C_IN : C_OUT));
                float p2 = ex2f(sfr[nt][2] + ((col    ) <= row0g + 8 ? C_IN : C_OUT));
                float p3 = ex2f(sfr[nt][3] + ((col + 1) <= row0g + 8 ? C_IN : C_OUT));
                l0 += p0 + p1;
                l1 += p2 + p3;
                pa[half16 * 2]     = packh2(p0, p1);
                pa[half16 * 2 + 1] = packh2(p2, p3);
            }
            const int k0 = kk * 16;
            #pragma unroll
            for (int dp = 0; dp < 4; dp++) {
                uint32_t vr[4];
                ldsm_x4_t(vr, vs_s + (uint32_t)((k0 + vV_row) * QLD + dp * 16 + vV_col) * 2);
                mma16816(oacc[2 * dp],     pa, vr);
                mma16816(oacc[2 * dp + 1], pa, vr + 2);
            }
        }
        sidx = (sidx + 1 >= 3) ? 0 : sidx + 1;
    }

    l0 += __shfl_xor_sync(0xffffffffu, l0, 1);
    l0 += __shfl_xor_sync(0xffffffffu, l0, 2);
    l1 += __shfl_xor_sync(0xffffffffu, l1, 1);
    l1 += __shfl_xor_sync(0xffffffffu, l1, 2);
    const float invl0 = 1.f / l0, invl1 = 1.f / l1;

    const int b = bh >> 4, h = bh & 15;
    const int r0 = qt * 128 + w * 16 + (lane >> 2);
    __half* d0p = out + ((size_t)(b * SEQ + r0    )) * Hh + h * Dd;
    __half* d1p = out + ((size_t)(b * SEQ + r0 + 8)) * Hh + h * Dd;
    #pragma unroll
    for (int nt = 0; nt < 8; nt++) {
        int col = nt * 8 + colb;
        *(__half2*)&d0p[col] = __floats2half2_rn(oacc[nt][0] * invl0, oacc[nt][1] * invl0);
        *(__half2*)&d1p[col] = __floats2half2_rn(oacc[nt][2] * invl1, oacc[nt][3] * invl1);
    }
}

// ---------------------------------------------------------------------------
extern "C" void kernel_launch(void* const* d_in, const int* in_sizes, int n_in,
                              void* d_out, int out_size)
{
    const float* hs   = (const float*)d_in[0];
    const float* cosT = (const float*)d_in[1];
    const float* sinT = (const float*)d_in[2];
    const float* Wq   = (const float*)d_in[3];
    const float* bq   = (const float*)d_in[4];
    const float* Wk   = (const float*)d_in[5];
    const float* bk   = (const float*)d_in[6];
    const float* Wv   = (const float*)d_in[7];
    const float* bv   = (const float*)d_in[8];
    const float* Wo   = (const float*)d_in[9];
    const float* bo   = (const float*)d_in[10];
    const float* rw   = (const float*)d_in[11];
    float* out = (float*)d_out;

    float* f32 = nullptr;  cudaGetSymbolAddress((void**)&f32, g_f32);
    __half* f16 = nullptr; cudaGetSymbolAddress((void**)&f16, g_f16);

    const size_t SZ = SZc;
    const size_t WZ = WZc;
    __half* qlinH = (__half*)f32;
    __half* klinH = qlinH + SZ;
    __half* vlinH = klinH + SZ;

    __half* hs_h  = f16;
    __half* Wq_h  = f16 + SZ;
    __half* Wk_h  = Wq_h + WZ;
    __half* Wv_h  = Wk_h + WZ;
    __half* Wo_h  = Wv_h + WZ;
    __half* qT    = Wo_h + WZ;
    __half* kT    = qT + SZ;
    __half* vT    = kT + SZ;
    __half* attn  = vT + SZ;

    cudaFuncSetAttribute(flash_mma_kernel,
                         cudaFuncAttributeMaxDynamicSharedMemorySize, FSM_BYTES);
    cudaFuncSetAttribute(gemm_mma_kernel,
                         cudaFuncAttributeMaxDynamicSharedMemorySize, GEMM_SMEM);

    f2h_all_kernel<<<(int)((SZ + 4 * WZ) / 1024), 256>>>(hs, Wq, Wk, Wv, Wo, f16);

    dim3 gqkv(Hh / 128, Mtok / 128, 3);
    gemm_mma_kernel<<<gqkv, 256, GEMM_SMEM>>>(hs_h, Wq_h, Wk_h, Wv_h,
                                              qlinH, klinH, vlinH,
                                              nullptr, nullptr);

    normrope_kernel<<<Mtok, 256>>>(qlinH, klinH, vlinH, bq, bk, bv,
                                   cosT, sinT, rw, qT, kT, vT);

    dim3 fg(SEQ / 128, Bb * NHd);
    flash_mma_kernel<<<fg, 256, FSM_BYTES>>>(qT, kT, vT, attn);

    dim3 gout(Hh / 128, Mtok / 128, 1);
    gemm_mma_kernel<<<gout, 256, GEMM_SMEM>>>(attn, Wo_h, Wo_h, Wo_h,
                                              nullptr, nullptr, nullptr,
                                              out, bo);
}

// round 15
// speedup vs baseline: 1.0630x; 1.0630x over previous
#include <cuda_runtime.h>
#include <cuda_fp16.h>
#include <math.h>
#include <stdint.h>

#define Bb    2
#define SEQ   2048
#define Hh    1024
#define NHd   16
#define Dd    64
#define Mtok  4096

__device__ float  g_f32[(size_t)3 * Mtok * Hh];   // reused as half qlin/klin/vlin
__device__ __half g_f16[(size_t)(4 + 4 + 12 + 4) * 1024 * 1024];

__device__ __forceinline__ void cp_async16(void* smem, const void* gmem) {
    unsigned saddr = (unsigned)__cvta_generic_to_shared(smem);
    asm volatile("cp.async.cg.shared.global [%0], [%1], 16;\n" :: "r"(saddr), "l"(gmem));
}
__device__ __forceinline__ void cp_commit() { asm volatile("cp.async.commit_group;\n"); }
template <int N>
__device__ __forceinline__ void cp_wait() { asm volatile("cp.async.wait_group %0;\n" :: "n"(N)); }

__device__ __forceinline__ void ldsm_x4(uint32_t* r, uint32_t saddr) {
    asm volatile("ldmatrix.sync.aligned.m8n8.x4.shared.b16 {%0,%1,%2,%3}, [%4];"
                 : "=r"(r[0]), "=r"(r[1]), "=r"(r[2]), "=r"(r[3]) : "r"(saddr));
}
__device__ __forceinline__ void ldsm_x4_t(uint32_t* r, uint32_t saddr) {
    asm volatile("ldmatrix.sync.aligned.m8n8.x4.trans.shared.b16 {%0,%1,%2,%3}, [%4];"
                 : "=r"(r[0]), "=r"(r[1]), "=r"(r[2]), "=r"(r[3]) : "r"(saddr));
}
__device__ __forceinline__ void mma16816(float* c, const uint32_t* a, const uint32_t* b) {
    asm volatile(
        "mma.sync.aligned.m16n8k16.row.col.f32.f16.f16.f32 "
        "{%0,%1,%2,%3}, {%4,%5,%6,%7}, {%8,%9}, {%0,%1,%2,%3};"
        : "+f"(c[0]), "+f"(c[1]), "+f"(c[2]), "+f"(c[3])
        : "r"(a[0]), "r"(a[1]), "r"(a[2]), "r"(a[3]), "r"(b[0]), "r"(b[1]));
}
__device__ __forceinline__ uint32_t packh2(float x, float y) {
    __half2 h = __floats2half2_rn(x, y);
    return *(uint32_t*)&h;
}
__device__ __forceinline__ float ex2f(float x) {
    float y; asm("ex2.approx.f32 %0, %1;" : "=f"(y) : "f"(x)); return y;
}

// ---------------------------------------------------------------------------
// fused fp32->fp16 conversion: 8 elems/thread (2x float4 in, 1x float4 out)
// ---------------------------------------------------------------------------
#define SZc ((size_t)Mtok * Hh)
#define WZc ((size_t)Hh * Hh)
__global__ __launch_bounds__(256)
void f2h_all_kernel(const float* __restrict__ hs,
                    const float* __restrict__ Wq, const float* __restrict__ Wk,
                    const float* __restrict__ Wv, const float* __restrict__ Wo,
                    __half* __restrict__ dst)
{
    size_t i8 = ((size_t)blockIdx.x * 256 + threadIdx.x) * 8;
    const float* s;
    if (i8 < SZc) s = &hs[i8];
    else {
        size_t wo = i8 - SZc;
        s = (wo < WZc)     ? &Wq[wo]
          : (wo < 2 * WZc) ? &Wk[wo - WZc]
          : (wo < 3 * WZc) ? &Wv[wo - 2 * WZc]
                           : &Wo[wo - 3 * WZc];
    }
    float4 v0 = *(const float4*)s;
    float4 v1 = *(const float4*)(s + 4);
    __half2 h[4];
    h[0] = __floats2half2_rn(v0.x, v0.y);
    h[1] = __floats2half2_rn(v0.z, v0.w);
    h[2] = __floats2half2_rn(v1.x, v1.y);
    h[3] = __floats2half2_rn(v1.z, v1.w);
    *(float4*)&dst[i8] = *(float4*)h;
}

// ---------------------------------------------------------------------------
// Raw-mma fp16 GEMM (R13 best): 128x128 CTA tile, 8 warps x (32x64), BK=32,
// 4-stage cp.async (wait<2>), register epilogue.
// ---------------------------------------------------------------------------
#define GBK  32
#define GLDG 40
#define GSTG (128 * GLDG)
#define GNS  4
#define GEMM_SMEM (2 * GNS * GSTG * 2)   // 81920
#define NITER 32

__global__ __launch_bounds__(256, 2)
void gemm_mma_kernel(const __half* __restrict__ A,
                     const __half* __restrict__ W0, const __half* __restrict__ W1,
                     const __half* __restrict__ W2,
                     __half* __restrict__ H0, __half* __restrict__ H1,
                     __half* __restrict__ H2,
                     float* __restrict__ F, const float* __restrict__ bias)
{
    extern __shared__ __align__(16) __half gsm[];
    __half* As = gsm;                    // [4][GSTG]
    __half* Bs = gsm + GNS * GSTG;       // [4][GSTG]

    const __half* W = (blockIdx.z == 0) ? W0 : (blockIdx.z == 1) ? W1 : W2;
    __half*       H = (blockIdx.z == 0) ? H0 : (blockIdx.z == 1) ? H1 : H2;

    const int tid  = threadIdx.x;
    const int w    = tid >> 5;
    const int lane = tid & 31;
    const int wr = w & 3;
    const int wc = w >> 2;
    const int bm = blockIdx.y * 128, bn = blockIdx.x * 128;
    const int K = 1024;

    float acc[2][8][4];
    #pragma unroll
    for (int m = 0; m < 2; m++)
        #pragma unroll
        for (int n = 0; n < 8; n++)
            #pragma unroll
            for (int j = 0; j < 4; j++) acc[m][n][j] = 0.f;

    const int lr = tid >> 2;
    const int lc = (tid & 3) * 8;

    // prefetch stages 0..2
    #pragma unroll
    for (int st = 0; st < 3; st++) {
        const int k0 = st * GBK;
        #pragma unroll
        for (int i = 0; i < 2; i++) {
            int r = lr + i * 64;
            cp_async16(&As[st * GSTG + r * GLDG + lc], &A[(size_t)(bm + r) * K + k0 + lc]);
            cp_async16(&Bs[st * GSTG + r * GLDG + lc], &W[(size_t)(bn + r) * K + k0 + lc]);
        }
        cp_commit();
    }

    const uint32_t as_b = (uint32_t)__cvta_generic_to_shared(As);
    const uint32_t bs_b = (uint32_t)__cvta_generic_to_shared(Bs);

    const int aA_row = wr * 32 + (lane & 15);
    const int aA_col = 8 * (lane >> 4);
    const int bB_row = wc * 64 + (lane & 7) + 8 * (lane >> 4);
    const int bB_col = 8 * ((lane >> 3) & 1);

    int sidx = 0;
    for (int it = 0; it < NITER; it++) {
        if (it < NITER - 2)      cp_wait<2>();
        else if (it < NITER - 1) cp_wait<1>();
        else                     cp_wait<0>();
        __syncthreads();

        if (it + 3 < NITER) {
            const int st = (sidx + 3) & 3;
            const int k0 = (it + 3) * GBK;
            #pragma unroll
            for (int i = 0; i < 2; i++) {
                int r = lr + i * 64;
                cp_async16(&As[st * GSTG + r * GLDG + lc], &A[(size_t)(bm + r) * K + k0 + lc]);
                cp_async16(&Bs[st * GSTG + r * GLDG + lc], &W[(size_t)(bn + r) * K + k0 + lc]);
            }
            cp_commit();
        }

        const uint32_t as_s = as_b + (uint32_t)(sidx * GSTG) * 2;
        const uint32_t bs_s = bs_b + (uint32_t)(sidx * GSTG) * 2;

        #pragma unroll
        for (int kk = 0; kk < 2; kk++) {
            const int kd = kk * 16;
            uint32_t af[2][4];
            #pragma unroll
            for (int m = 0; m < 2; m++)
                ldsm_x4(af[m], as_s + (uint32_t)((aA_row + m * 16) * GLDG + kd + aA_col) * 2);
            #pragma unroll
            for (int np = 0; np < 4; np++) {
                uint32_t bf[4];
                ldsm_x4(bf, bs_s + (uint32_t)((bB_row + np * 16) * GLDG + kd + bB_col) * 2);
                mma16816(acc[0][np * 2],     af[0], bf);
                mma16816(acc[0][np * 2 + 1], af[0], bf + 2);
                mma16816(acc[1][np * 2],     af[1], bf);
                mma16816(acc[1][np * 2 + 1], af[1], bf + 2);
            }
        }
        sidx = (sidx + 1) & 3;
    }

    const int colb = 2 * (lane & 3);
    if (H != nullptr) {
        #pragma unroll
        for (int m = 0; m < 2; m++) {
            const int r0 = bm + wr * 32 + m * 16 + (lane >> 2);
            __half* p0 = &H[(size_t)r0 * 1024 + bn + wc * 64];
            __half* p1 = &H[(size_t)(r0 + 8) * 1024 + bn + wc * 64];
            #pragma unroll
            for (int n = 0; n < 8; n++) {
                *(uint32_t*)&p0[n * 8 + colb] = packh2(acc[m][n][0], acc[m][n][1]);
                *(uint32_t*)&p1[n * 8 + colb] = packh2(acc[m][n][2], acc[m][n][3]);
            }
        }
    } else {
        #pragma unroll
        for (int m = 0; m < 2; m++) {
            const int r0 = bm + wr * 32 + m * 16 + (lane >> 2);
            float* p0 = &F[(size_t)r0 * 1024 + bn + wc * 64];
            float* p1 = &F[(size_t)(r0 + 8) * 1024 + bn + wc * 64];
            const float* bp = &bias[bn + wc * 64];
            #pragma unroll
            for (int n = 0; n < 8; n++) {
                float b0 = bp[n * 8 + colb], b1 = bp[n * 8 + colb + 1];
                float2 o0 = { acc[m][n][0] + b0, acc[m][n][1] + b1 };
                float2 o1 = { acc[m][n][2] + b0, acc[m][n][3] + b1 };
                *(float2*)&p0[n * 8 + colb] = o0;
                *(float2*)&p1[n * 8 + colb] = o1;
            }
        }
    }
}

// ---------------------------------------------------------------------------
// RMSNorm + bias + RoPE: 2 tokens per 256-thread block, 128 threads/token,
// 8 contiguous elems/thread (16B half loads/stores). Outputs half q/k/v in
// [B,NH,S,D]; q pre-scaled by 0.125*log2(e).
// ---------------------------------------------------------------------------
#define QSCALE (0.125f * 1.44269504089f)

__global__ __launch_bounds__(256)
void normrope_kernel(const __half* __restrict__ qlin, const __half* __restrict__ klin,
                     const __half* __restrict__ vlin,
                     const float* __restrict__ bq, const float* __restrict__ bk,
                     const float* __restrict__ bv,
                     const float* __restrict__ cosT, const float* __restrict__ sinT,
                     const float* __restrict__ w,
                     __half* __restrict__ qo, __half* __restrict__ ko, __half* __restrict__ vo)
{
    const int tid  = threadIdx.x;
    const int sub  = tid >> 7;                 // token within block (0/1)
    const int ltid = tid & 127;
    const int t = blockIdx.x * 2 + sub;
    const int b = t >> 11;
    const int s = t & 2047;
    const int i0 = ltid * 8;                   // 8 contiguous elements

    __shared__ float sq[2][1024], sk[2][1024];
    __shared__ float red[2][8];
    __shared__ float rqs[2], rks[2];

    float sumq = 0.f, sumk = 0.f;
    {
        float4 qv4 = *(const float4*)&qlin[(size_t)t * 1024 + i0];   // 8 halfs
        float4 kv4 = *(const float4*)&klin[(size_t)t * 1024 + i0];
        const __half2* qh = (const __half2*)&qv4;
        const __half2* kh = (const __half2*)&kv4;
        #pragma unroll
        for (int j = 0; j < 4; j++) {
            float2 qf = __half22float2(qh[j]);
            float2 kf = __half22float2(kh[j]);
            float bq0 = bq[i0 + j * 2], bq1 = bq[i0 + j * 2 + 1];
            float bk0 = bk[i0 + j * 2], bk1 = bk[i0 + j * 2 + 1];
            float x0 = qf.x + bq0, x1 = qf.y + bq1;
            float y0 = kf.x + bk0, y1 = kf.y + bk1;
            sq[sub][i0 + j * 2] = x0; sq[sub][i0 + j * 2 + 1] = x1;
            sk[sub][i0 + j * 2] = y0; sk[sub][i0 + j * 2 + 1] = y1;
            sumq += x0 * x0 + x1 * x1;
            sumk += y0 * y0 + y1 * y1;
        }
    }
    #pragma unroll
    for (int off = 16; off > 0; off >>= 1) {
        sumq += __shfl_down_sync(0xffffffffu, sumq, off);
        sumk += __shfl_down_sync(0xffffffffu, sumk, off);
    }
    if ((ltid & 31) == 0) {
        red[sub][ltid >> 5]     = sumq;
        red[sub][4 + (ltid >> 5)] = sumk;
    }
    __syncthreads();
    if (ltid == 0) {
        float a = red[sub][0] + red[sub][1] + red[sub][2] + red[sub][3];
        float c = red[sub][4] + red[sub][5] + red[sub][6] + red[sub][7];
        rqs[sub] = rsqrtf(a * (1.0f / 1024.0f) + 1e-6f);
        rks[sub] = rsqrtf(c * (1.0f / 1024.0f) + 1e-6f);
    }
    __syncthreads();
    const float rq = rqs[sub], rk = rks[sub];

    {
        const int h = i0 >> 6, d = i0 & 63;    // 8 elems within one head half
        const int pbase = (d < 32) ? i0 + 32 : i0 - 32;
        const float sign = (d < 32) ? -1.f : 1.f;
        __half2 outq[4], outk[4], outv[4];
        float4 vv4 = *(const float4*)&vlin[(size_t)t * 1024 + i0];
        const __half2* vh = (const __half2*)&vv4;
        #pragma unroll
        for (int j = 0; j < 8; j += 2) {
            float cs0 = cosT[s * 64 + d + j],     sn0 = sinT[s * 64 + d + j];
            float cs1 = cosT[s * 64 + d + j + 1], sn1 = sinT[s * 64 + d + j + 1];
            float w0 = w[i0 + j], w1 = w[i0 + j + 1];
            float wp0 = w[pbase + j], wp1 = w[pbase + j + 1];
            float qx0 = sq[sub][i0 + j] * rq * w0,     qp0 = sq[sub][pbase + j] * rq * wp0;
            float qx1 = sq[sub][i0 + j + 1] * rq * w1, qp1 = sq[sub][pbase + j + 1] * rq * wp1;
            float kx0 = sk[sub][i0 + j] * rk * w0,     kp0 = sk[sub][pbase + j] * rk * wp0;
            float kx1 = sk[sub][i0 + j + 1] * rk * w1, kp1 = sk[sub][pbase + j + 1] * rk * wp1;
            outq[j / 2] = __floats2half2_rn((qx0 * cs0 + sign * qp0 * sn0) * QSCALE,
                                            (qx1 * cs1 + sign * qp1 * sn1) * QSCALE);
            outk[j / 2] = __floats2half2_rn(kx0 * cs0 + sign * kp0 * sn0,
                                            kx1 * cs1 + sign * kp1 * sn1);
            float2 vf = __half22float2(vh[j / 2]);
            outv[j / 2] = __floats2half2_rn(vf.x + bv[i0 + j], vf.y + bv[i0 + j + 1]);
        }
        size_t oidx = ((size_t)(b * NHd + h) * SEQ + s) * Dd + d;
        *(float4*)&qo[oidx] = *(float4*)outq;
        *(float4*)&ko[oidx] = *(float4*)outk;
        *(float4*)&vo[oidx] = *(float4*)outv;
    }
}

// ---------------------------------------------------------------------------
// Flash attention (best measured config, unchanged): raw mma.sync, 8 warps x
// 16 q-rows, register S/P, exp2-domain scores, 3-stage K/V ring.
// ---------------------------------------------------------------------------
#define QLD 72
#define FTILE (64 * QLD)
#define FSM_BYTES ((128 * QLD + 6 * FTILE) * 2)    // 73728
#define C_IN  (-2.88539008178f)
#define C_OUT (-4.32808512267f)

__global__ __launch_bounds__(256, 2)
void flash_mma_kernel(const __half* __restrict__ q, const __half* __restrict__ k,
                      const __half* __restrict__ v, __half* __restrict__ out)
{
    extern __shared__ __align__(16) char smraw[];
    __half* Qs = (__half*)smraw;               // [128][QLD]
    __half* Ks = Qs + 128 * QLD;               // [3][64][QLD]
    __half* Vs = Ks + 3 * FTILE;               // [3][64][QLD]

    const int tid  = threadIdx.x;
    const int w    = tid >> 5;
    const int lane = tid & 31;
    const int bh   = blockIdx.y;
    const int qt   = blockIdx.x;
    const __half* kb = k + (size_t)bh * SEQ * Dd;
    const __half* vb = v + (size_t)bh * SEQ * Dd;
    const __half* qb = q + ((size_t)bh * SEQ + qt * 128) * Dd;

    {
        int r = tid >> 1, c0 = (tid & 1) * 32;
        #pragma unroll
        for (int i = 0; i < 4; i++)
            cp_async16(&Qs[r * QLD + c0 + i * 8], &qb[(size_t)r * Dd + c0 + i * 8]);
        int lr = tid >> 2, lc = (tid & 3) * 16;
        #pragma unroll
        for (int st = 0; st < 2; st++) {
            #pragma unroll
            for (int i = 0; i < 2; i++) {
                cp_async16(&Ks[st * FTILE + lr * QLD + lc + i * 8],
                           &kb[(size_t)(st * 64 + lr) * Dd + lc + i * 8]);
                cp_async16(&Vs[st * FTILE + lr * QLD + lc + i * 8],
                           &vb[(size_t)(st * 64 + lr) * Dd + lc + i * 8]);
            }
            cp_commit();
        }
    }

    const uint32_t qs_b = (uint32_t)__cvta_generic_to_shared(Qs);
    const uint32_t ks_b = (uint32_t)__cvta_generic_to_shared(Ks);
    const uint32_t vs_b = (uint32_t)__cvta_generic_to_shared(Vs);

    cp_wait<1>();
    __syncthreads();

    uint32_t qa[4][4];
    {
        int r = w * 16 + (lane & 15);
        int cbase = 8 * (lane >> 4);
        #pragma unroll
        for (int kk = 0; kk < 4; kk++)
            ldsm_x4(qa[kk], qs_b + (uint32_t)(r * QLD + kk * 16 + cbase) * 2);
    }

    float oacc[8][4];
    #pragma unroll
    for (int i = 0; i < 8; i++)
        #pragma unroll
        for (int j = 0; j < 4; j++) oacc[i][j] = 0.f;
    float l0 = 0.f, l1 = 0.f;

    const int colb  = 2 * (lane & 3);
    const int row0g = qt * 128 + w * 16 + (lane >> 2);

    const int kK_row = (lane & 7) + 8 * (lane >> 4);
    const int kK_col = 8 * ((lane >> 3) & 1);
    const int vV_row = (lane & 7) + 8 * ((lane >> 3) & 1);
    const int vV_col = 8 * (lane >> 4);

    const int NT = SEQ / 64;
    int sidx = 0;
    for (int t = 0; t < NT; t++) {
        const int kt = t * 64;
        if (t < NT - 1) cp_wait<1>(); else cp_wait<0>();
        __syncthreads();

        if (t + 2 < NT) {
            const int st = (sidx + 2 >= 3) ? sidx - 1 : sidx + 2;
            const int kn = kt + 128;
            __half* Kd = &Ks[st * FTILE];
            __half* Vd = &Vs[st * FTILE];
            int lr = tid >> 2, lc = (tid & 3) * 16;
            #pragma unroll
            for (int i = 0; i < 2; i++) {
                cp_async16(&Kd[lr * QLD + lc + i * 8], &kb[(size_t)(kn + lr) * Dd + lc + i * 8]);
                cp_async16(&Vd[lr * QLD + lc + i * 8], &vb[(size_t)(kn + lr) * Dd + lc + i * 8]);
            }
            cp_commit();
        }

        const uint32_t ks_s = ks_b + (uint32_t)(sidx * FTILE) * 2;
        const uint32_t vs_s = vs_b + (uint32_t)(sidx * FTILE) * 2;

        float sfr[8][4];
        #pragma unroll
        for (int i = 0; i < 8; i++)
            #pragma unroll
            for (int j = 0; j < 4; j++) sfr[i][j] = 0.f;

        #pragma unroll
        for (int kk = 0; kk < 4; kk++) {
            const int d0 = kk * 16;
            #pragma unroll
            for (int np = 0; np < 4; np++) {
                uint32_t kr[4];
                ldsm_x4(kr, ks_s + (uint32_t)((np * 16 + kK_row) * QLD + d0 + kK_col) * 2);
                mma16816(sfr[2 * np],     qa[kk], kr);
                mma16816(sfr[2 * np + 1], qa[kk], kr + 2);
            }
        }

        #pragma unroll
        for (int kk = 0; kk < 4; kk++) {
            uint32_t pa[4];
            #pragma unroll
            for (int half16 = 0; half16 < 2; half16++) {
                const int nt = kk * 2 + half16;
                int col = kt + nt * 8 + colb;
                float p0 = ex2f(sfr[nt][0] + ((col    ) <= row0g     ? C_IN : C_OUT));
                float p1 = ex2f(sfr[nt][1] + ((col + 1) <= row0g     ? C_IN : C_OUT));
                float p2 = ex2f(sfr[nt][2] + ((col    ) <= row0g + 8 ? C_IN : C_OUT));
                float p3 = ex2f(sfr[nt][3] + ((col + 1) <= row0g + 8 ? C_IN : C_OUT));
                l0 += p0 + p1;
                l1 += p2 + p3;
                pa[half16 * 2]     = packh2(p0, p1);
                pa[half16 * 2 + 1] = packh2(p2, p3);
            }
            const int k0 = kk * 16;
            #pragma unroll
            for (int dp = 0; dp < 4; dp++) {
                uint32_t vr[4];
                ldsm_x4_t(vr, vs_s + (uint32_t)((k0 + vV_row) * QLD + dp * 16 + vV_col) * 2);
                mma16816(oacc[2 * dp],     pa, vr);
                mma16816(oacc[2 * dp + 1], pa, vr + 2);
            }
        }
        sidx = (sidx + 1 >= 3) ? 0 : sidx + 1;
    }

    l0 += __shfl_xor_sync(0xffffffffu, l0, 1);
    l0 += __shfl_xor_sync(0xffffffffu, l0, 2);
    l1 += __shfl_xor_sync(0xffffffffu, l1, 1);
    l1 += __shfl_xor_sync(0xffffffffu, l1, 2);
    const float invl0 = 1.f / l0, invl1 = 1.f / l1;

    const int b = bh >> 4, h = bh & 15;
    const int r0 = qt * 128 + w * 16 + (lane >> 2);
    __half* d0p = out + ((size_t)(b * SEQ + r0    )) * Hh + h * Dd;
    __half* d1p = out + ((size_t)(b * SEQ + r0 + 8)) * Hh + h * Dd;
    #pragma unroll
    for (int nt = 0; nt < 8; nt++) {
        int col = nt * 8 + colb;
        *(__half2*)&d0p[col] = __floats2half2_rn(oacc[nt][0] * invl0, oacc[nt][1] * invl0);
        *(__half2*)&d1p[col] = __floats2half2_rn(oacc[nt][2] * invl1, oacc[nt][3] * invl1);
    }
}

// ---------------------------------------------------------------------------
extern "C" void kernel_launch(void* const* d_in, const int* in_sizes, int n_in,
                              void* d_out, int out_size)
{
    const float* hs   = (const float*)d_in[0];
    const float* cosT = (const float*)d_in[1];
    const float* sinT = (const float*)d_in[2];
    const float* Wq   = (const float*)d_in[3];
    const float* bq   = (const float*)d_in[4];
    const float* Wk   = (const float*)d_in[5];
    const float* bk   = (const float*)d_in[6];
    const float* Wv   = (const float*)d_in[7];
    const float* bv   = (const float*)d_in[8];
    const float* Wo   = (const float*)d_in[9];
    const float* bo   = (const float*)d_in[10];
    const float* rw   = (const float*)d_in[11];
    float* out = (float*)d_out;

    float* f32 = nullptr;  cudaGetSymbolAddress((void**)&f32, g_f32);
    __half* f16 = nullptr; cudaGetSymbolAddress((void**)&f16, g_f16);

    const size_t SZ = SZc;
    const size_t WZ = WZc;
    __half* qlinH = (__half*)f32;
    __half* klinH = qlinH + SZ;
    __half* vlinH = klinH + SZ;

    __half* hs_h  = f16;
    __half* Wq_h  = f16 + SZ;
    __half* Wk_h  = Wq_h + WZ;
    __half* Wv_h  = Wk_h + WZ;
    __half* Wo_h  = Wv_h + WZ;
    __half* qT    = Wo_h + WZ;
    __half* kT    = qT + SZ;
    __half* vT    = kT + SZ;
    __half* attn  = vT + SZ;

    cudaFuncSetAttribute(flash_mma_kernel,
                         cudaFuncAttributeMaxDynamicSharedMemorySize, FSM_BYTES);
    cudaFuncSetAttribute(gemm_mma_kernel,
                         cudaFuncAttributeMaxDynamicSharedMemorySize, GEMM_SMEM);

    // 8M elems, 8 per thread
    f2h_all_kernel<<<(int)((SZ + 4 * WZ) / 2048), 256>>>(hs, Wq, Wk, Wv, Wo, f16);

    dim3 gqkv(Hh / 128, Mtok / 128, 3);
    gemm_mma_kernel<<<gqkv, 256, GEMM_SMEM>>>(hs_h, Wq_h, Wk_h, Wv_h,
                                              qlinH, klinH, vlinH,
                                              nullptr, nullptr);

    normrope_kernel<<<Mtok / 2, 256>>>(qlinH, klinH, vlinH, bq, bk, bv,
                                       cosT, sinT, rw, qT, kT, vT);

    dim3 fg(SEQ / 128, Bb * NHd);
    flash_mma_kernel<<<fg, 256, FSM_BYTES>>>(qT, kT, vT, attn);

    dim3 gout(Hh / 128, Mtok / 128, 1);
    gemm_mma_kernel<<<gout, 256, GEMM_SMEM>>>(attn, Wo_h, Wo_h, Wo_h,
                                              nullptr, nullptr, nullptr,
                                              out, bo);
}

// round 16
// speedup vs baseline: 1.1336x; 1.0664x over previous
#include <cuda_runtime.h>
#include <cuda_fp16.h>
#include <math.h>
#include <stdint.h>

#define Bb    2
#define SEQ   2048
#define Hh    1024
#define NHd   16
#define Dd    64
#define Mtok  4096

__device__ float  g_f32[(size_t)3 * Mtok * Hh];   // reused as half qlin/klin/vlin
__device__ __half g_f16[(size_t)(4 + 4 + 12 + 4) * 1024 * 1024];

__device__ __forceinline__ void cp_async16(void* smem, const void* gmem) {
    unsigned saddr = (unsigned)__cvta_generic_to_shared(smem);
    asm volatile("cp.async.cg.shared.global [%0], [%1], 16;\n" :: "r"(saddr), "l"(gmem));
}
__device__ __forceinline__ void cp_commit() { asm volatile("cp.async.commit_group;\n"); }
template <int N>
__device__ __forceinline__ void cp_wait() { asm volatile("cp.async.wait_group %0;\n" :: "n"(N)); }

__device__ __forceinline__ void ldsm_x4(uint32_t* r, uint32_t saddr) {
    asm volatile("ldmatrix.sync.aligned.m8n8.x4.shared.b16 {%0,%1,%2,%3}, [%4];"
                 : "=r"(r[0]), "=r"(r[1]), "=r"(r[2]), "=r"(r[3]) : "r"(saddr));
}
__device__ __forceinline__ void ldsm_x4_t(uint32_t* r, uint32_t saddr) {
    asm volatile("ldmatrix.sync.aligned.m8n8.x4.trans.shared.b16 {%0,%1,%2,%3}, [%4];"
                 : "=r"(r[0]), "=r"(r[1]), "=r"(r[2]), "=r"(r[3]) : "r"(saddr));
}
__device__ __forceinline__ void mma16816(float* c, const uint32_t* a, const uint32_t* b) {
    asm volatile(
        "mma.sync.aligned.m16n8k16.row.col.f32.f16.f16.f32 "
        "{%0,%1,%2,%3}, {%4,%5,%6,%7}, {%8,%9}, {%0,%1,%2,%3};"
        : "+f"(c[0]), "+f"(c[1]), "+f"(c[2]), "+f"(c[3])
        : "r"(a[0]), "r"(a[1]), "r"(a[2]), "r"(a[3]), "r"(b[0]), "r"(b[1]));
}
__device__ __forceinline__ uint32_t packh2(float x, float y) {
    __half2 h = __floats2half2_rn(x, y);
    return *(uint32_t*)&h;
}
__device__ __forceinline__ float ex2f(float x) {
    float y; asm("ex2.approx.f32 %0, %1;" : "=f"(y) : "f"(x)); return y;
}

// ---------------------------------------------------------------------------
// fused fp32->fp16 conversion: 8 elems/thread (2x LDG.128 -> 1x STG.128)
// ---------------------------------------------------------------------------
#define SZc ((size_t)Mtok * Hh)
#define WZc ((size_t)Hh * Hh)
__global__ __launch_bounds__(256)
void f2h_all_kernel(const float* __restrict__ hs,
                    const float* __restrict__ Wq, const float* __restrict__ Wk,
                    const float* __restrict__ Wv, const float* __restrict__ Wo,
                    __half* __restrict__ dst)
{
    size_t i8 = ((size_t)blockIdx.x * 256 + threadIdx.x) * 8;
    const float* s;
    if (i8 < SZc) s = &hs[i8];
    else {
        size_t wo = i8 - SZc;
        s = (wo < WZc)     ? &Wq[wo]
          : (wo < 2 * WZc) ? &Wk[wo - WZc]
          : (wo < 3 * WZc) ? &Wv[wo - 2 * WZc]
                           : &Wo[wo - 3 * WZc];
    }
    float4 v0 = *(const float4*)s;
    float4 v1 = *(const float4*)(s + 4);
    __half2 h[4];
    h[0] = __floats2half2_rn(v0.x, v0.y);
    h[1] = __floats2half2_rn(v0.z, v0.w);
    h[2] = __floats2half2_rn(v1.x, v1.y);
    h[3] = __floats2half2_rn(v1.z, v1.w);
    *(float4*)&dst[i8] = *(float4*)h;
}

// ---------------------------------------------------------------------------
// Raw-mma fp16 GEMM (R13 best): 128x128 CTA tile, 8 warps x (32x64), BK=32,
// 4-stage cp.async (wait<2>), register epilogue.
// ---------------------------------------------------------------------------
#define GBK  32
#define GLDG 40
#define GSTG (128 * GLDG)
#define GNS  4
#define GEMM_SMEM (2 * GNS * GSTG * 2)   // 81920
#define NITER 32

__global__ __launch_bounds__(256, 2)
void gemm_mma_kernel(const __half* __restrict__ A,
                     const __half* __restrict__ W0, const __half* __restrict__ W1,
                     const __half* __restrict__ W2,
                     __half* __restrict__ H0, __half* __restrict__ H1,
                     __half* __restrict__ H2,
                     float* __restrict__ F, const float* __restrict__ bias)
{
    extern __shared__ __align__(16) __half gsm[];
    __half* As = gsm;                    // [4][GSTG]
    __half* Bs = gsm + GNS * GSTG;       // [4][GSTG]

    const __half* W = (blockIdx.z == 0) ? W0 : (blockIdx.z == 1) ? W1 : W2;
    __half*       H = (blockIdx.z == 0) ? H0 : (blockIdx.z == 1) ? H1 : H2;

    const int tid  = threadIdx.x;
    const int w    = tid >> 5;
    const int lane = tid & 31;
    const int wr = w & 3;
    const int wc = w >> 2;
    const int bm = blockIdx.y * 128, bn = blockIdx.x * 128;
    const int K = 1024;

    float acc[2][8][4];
    #pragma unroll
    for (int m = 0; m < 2; m++)
        #pragma unroll
        for (int n = 0; n < 8; n++)
            #pragma unroll
            for (int j = 0; j < 4; j++) acc[m][n][j] = 0.f;

    const int lr = tid >> 2;
    const int lc = (tid & 3) * 8;

    // prefetch stages 0..2
    #pragma unroll
    for (int st = 0; st < 3; st++) {
        const int k0 = st * GBK;
        #pragma unroll
        for (int i = 0; i < 2; i++) {
            int r = lr + i * 64;
            cp_async16(&As[st * GSTG + r * GLDG + lc], &A[(size_t)(bm + r) * K + k0 + lc]);
            cp_async16(&Bs[st * GSTG + r * GLDG + lc], &W[(size_t)(bn + r) * K + k0 + lc]);
        }
        cp_commit();
    }

    const uint32_t as_b = (uint32_t)__cvta_generic_to_shared(As);
    const uint32_t bs_b = (uint32_t)__cvta_generic_to_shared(Bs);

    const int aA_row = wr * 32 + (lane & 15);
    const int aA_col = 8 * (lane >> 4);
    const int bB_row = wc * 64 + (lane & 7) + 8 * (lane >> 4);
    const int bB_col = 8 * ((lane >> 3) & 1);

    int sidx = 0;
    for (int it = 0; it < NITER; it++) {
        if (it < NITER - 2)      cp_wait<2>();
        else if (it < NITER - 1) cp_wait<1>();
        else                     cp_wait<0>();
        __syncthreads();

        if (it + 3 < NITER) {
            const int st = (sidx + 3) & 3;
            const int k0 = (it + 3) * GBK;
            #pragma unroll
            for (int i = 0; i < 2; i++) {
                int r = lr + i * 64;
                cp_async16(&As[st * GSTG + r * GLDG + lc], &A[(size_t)(bm + r) * K + k0 + lc]);
                cp_async16(&Bs[st * GSTG + r * GLDG + lc], &W[(size_t)(bn + r) * K + k0 + lc]);
            }
            cp_commit();
        }

        const uint32_t as_s = as_b + (uint32_t)(sidx * GSTG) * 2;
        const uint32_t bs_s = bs_b + (uint32_t)(sidx * GSTG) * 2;

        #pragma unroll
        for (int kk = 0; kk < 2; kk++) {
            const int kd = kk * 16;
            uint32_t af[2][4];
            #pragma unroll
            for (int m = 0; m < 2; m++)
                ldsm_x4(af[m], as_s + (uint32_t)((aA_row + m * 16) * GLDG + kd + aA_col) * 2);
            #pragma unroll
            for (int np = 0; np < 4; np++) {
                uint32_t bf[4];
                ldsm_x4(bf, bs_s + (uint32_t)((bB_row + np * 16) * GLDG + kd + bB_col) * 2);
                mma16816(acc[0][np * 2],     af[0], bf);
                mma16816(acc[0][np * 2 + 1], af[0], bf + 2);
                mma16816(acc[1][np * 2],     af[1], bf);
                mma16816(acc[1][np * 2 + 1], af[1], bf + 2);
            }
        }
        sidx = (sidx + 1) & 3;
    }

    const int colb = 2 * (lane & 3);
    if (H != nullptr) {
        #pragma unroll
        for (int m = 0; m < 2; m++) {
            const int r0 = bm + wr * 32 + m * 16 + (lane >> 2);
            __half* p0 = &H[(size_t)r0 * 1024 + bn + wc * 64];
            __half* p1 = &H[(size_t)(r0 + 8) * 1024 + bn + wc * 64];
            #pragma unroll
            for (int n = 0; n < 8; n++) {
                *(uint32_t*)&p0[n * 8 + colb] = packh2(acc[m][n][0], acc[m][n][1]);
                *(uint32_t*)&p1[n * 8 + colb] = packh2(acc[m][n][2], acc[m][n][3]);
            }
        }
    } else {
        #pragma unroll
        for (int m = 0; m < 2; m++) {
            const int r0 = bm + wr * 32 + m * 16 + (lane >> 2);
            float* p0 = &F[(size_t)r0 * 1024 + bn + wc * 64];
            float* p1 = &F[(size_t)(r0 + 8) * 1024 + bn + wc * 64];
            const float* bp = &bias[bn + wc * 64];
            #pragma unroll
            for (int n = 0; n < 8; n++) {
                float b0 = bp[n * 8 + colb], b1 = bp[n * 8 + colb + 1];
                float2 o0 = { acc[m][n][0] + b0, acc[m][n][1] + b1 };
                float2 o1 = { acc[m][n][2] + b0, acc[m][n][3] + b1 };
                *(float2*)&p0[n * 8 + colb] = o0;
                *(float2*)&p1[n * 8 + colb] = o1;
            }
        }
    }
}

// ---------------------------------------------------------------------------
// RMSNorm + bias + RoPE (R13 version — best measured): 1 token/block,
// 4 contiguous elems/thread, float4 loads of biases/cos/sin/w.
// Outputs half q/k/v in [B,NH,S,D]; q pre-scaled by 0.125*log2(e).
// ---------------------------------------------------------------------------
#define QSCALE (0.125f * 1.44269504089f)

__global__ __launch_bounds__(256)
void normrope_kernel(const __half* __restrict__ qlin, const __half* __restrict__ klin,
                     const __half* __restrict__ vlin,
                     const float* __restrict__ bq, const float* __restrict__ bk,
                     const float* __restrict__ bv,
                     const float* __restrict__ cosT, const float* __restrict__ sinT,
                     const float* __restrict__ w,
                     __half* __restrict__ qo, __half* __restrict__ ko, __half* __restrict__ vo)
{
    const int t = blockIdx.x;
    const int b = t >> 11;
    const int s = t & 2047;
    const int tid = threadIdx.x;
    const int i0 = tid * 4;

    __shared__ float sq[1024], sk[1024];
    __shared__ float red[16];
    __shared__ float rqs, rks;

    float sumq = 0.f, sumk = 0.f;
    {
        __half2 q01 = *(const __half2*)&qlin[(size_t)t * 1024 + i0];
        __half2 q23 = *(const __half2*)&qlin[(size_t)t * 1024 + i0 + 2];
        __half2 k01 = *(const __half2*)&klin[(size_t)t * 1024 + i0];
        __half2 k23 = *(const __half2*)&klin[(size_t)t * 1024 + i0 + 2];
        float4 bq4 = *(const float4*)&bq[i0];
        float4 bk4 = *(const float4*)&bk[i0];
        float x0 = __half2float(q01.x) + bq4.x, x1 = __half2float(q01.y) + bq4.y;
        float x2 = __half2float(q23.x) + bq4.z, x3 = __half2float(q23.y) + bq4.w;
        float y0 = __half2float(k01.x) + bk4.x, y1 = __half2float(k01.y) + bk4.y;
        float y2 = __half2float(k23.x) + bk4.z, y3 = __half2float(k23.y) + bk4.w;
        sq[i0] = x0; sq[i0 + 1] = x1; sq[i0 + 2] = x2; sq[i0 + 3] = x3;
        sk[i0] = y0; sk[i0 + 1] = y1; sk[i0 + 2] = y2; sk[i0 + 3] = y3;
        sumq = (x0 * x0 + x1 * x1) + (x2 * x2 + x3 * x3);
        sumk = (y0 * y0 + y1 * y1) + (y2 * y2 + y3 * y3);
    }
    #pragma unroll
    for (int off = 16; off > 0; off >>= 1) {
        sumq += __shfl_down_sync(0xffffffffu, sumq, off);
        sumk += __shfl_down_sync(0xffffffffu, sumk, off);
    }
    if ((tid & 31) == 0) { red[tid >> 5] = sumq; red[8 + (tid >> 5)] = sumk; }
    __syncthreads();
    if (tid == 0) {
        float a = 0.f, c = 0.f;
        #pragma unroll
        for (int i2 = 0; i2 < 8; i2++) { a += red[i2]; c += red[8 + i2]; }
        rqs = rsqrtf(a * (1.0f / 1024.0f) + 1e-6f);
        rks = rsqrtf(c * (1.0f / 1024.0f) + 1e-6f);
    }
    __syncthreads();
    const float rq = rqs, rk = rks;

    {
        const int h = i0 >> 6, d = i0 & 63;
        const int pbase = (d < 32) ? i0 + 32 : i0 - 32;
        const float sign = (d < 32) ? -1.f : 1.f;
        float4 cs4 = *(const float4*)&cosT[s * 64 + d];
        float4 sn4 = *(const float4*)&sinT[s * 64 + d];
        float4 w4  = *(const float4*)&w[i0];
        float4 wp4 = *(const float4*)&w[pbase];
        float qv[4], kv[4];
        #pragma unroll
        for (int j = 0; j < 4; j++) {
            float wv = (&w4.x)[j], wp = (&wp4.x)[j];
            float cs = (&cs4.x)[j], sn = (&sn4.x)[j];
            float qx = sq[i0 + j] * rq * wv, qp = sq[pbase + j] * rq * wp;
            float kx = sk[i0 + j] * rk * wv, kp = sk[pbase + j] * rk * wp;
            qv[j] = (qx * cs + sign * qp * sn) * QSCALE;
            kv[j] = kx * cs + sign * kp * sn;
        }
        size_t oidx = ((size_t)(b * NHd + h) * SEQ + s) * Dd + d;
        *(__half2*)&qo[oidx]     = __floats2half2_rn(qv[0], qv[1]);
        *(__half2*)&qo[oidx + 2] = __floats2half2_rn(qv[2], qv[3]);
        *(__half2*)&ko[oidx]     = __floats2half2_rn(kv[0], kv[1]);
        *(__half2*)&ko[oidx + 2] = __floats2half2_rn(kv[2], kv[3]);
        __half2 v01 = *(const __half2*)&vlin[(size_t)t * 1024 + i0];
        __half2 v23 = *(const __half2*)&vlin[(size_t)t * 1024 + i0 + 2];
        float4 bv4 = *(const float4*)&bv[i0];
        *(__half2*)&vo[oidx]     = __floats2half2_rn(__half2float(v01.x) + bv4.x,
                                                     __half2float(v01.y) + bv4.y);
        *(__half2*)&vo[oidx + 2] = __floats2half2_rn(__half2float(v23.x) + bv4.z,
                                                     __half2float(v23.y) + bv4.w);
    }
}

// ---------------------------------------------------------------------------
// Flash attention (best measured config, unchanged): raw mma.sync, 8 warps x
// 16 q-rows, register S/P, exp2-domain scores, 3-stage K/V ring.
// ---------------------------------------------------------------------------
#define QLD 72
#define FTILE (64 * QLD)
#define FSM_BYTES ((128 * QLD + 6 * FTILE) * 2)    // 73728
#define C_IN  (-2.88539008178f)
#define C_OUT (-4.32808512267f)

__global__ __launch_bounds__(256, 2)
void flash_mma_kernel(const __half* __restrict__ q, const __half* __restrict__ k,
                      const __half* __restrict__ v, __half* __restrict__ out)
{
    extern __shared__ __align__(16) char smraw[];
    __half* Qs = (__half*)smraw;               // [128][QLD]
    __half* Ks = Qs + 128 * QLD;               // [3][64][QLD]
    __half* Vs = Ks + 3 * FTILE;               // [3][64][QLD]

    const int tid  = threadIdx.x;
    const int w    = tid >> 5;
    const int lane = tid & 31;
    const int bh   = blockIdx.y;
    const int qt   = blockIdx.x;
    const __half* kb = k + (size_t)bh * SEQ * Dd;
    const __half* vb = v + (size_t)bh * SEQ * Dd;
    const __half* qb = q + ((size_t)bh * SEQ + qt * 128) * Dd;

    {
        int r = tid >> 1, c0 = (tid & 1) * 32;
        #pragma unroll
        for (int i = 0; i < 4; i++)
            cp_async16(&Qs[r * QLD + c0 + i * 8], &qb[(size_t)r * Dd + c0 + i * 8]);
        int lr = tid >> 2, lc = (tid & 3) * 16;
        #pragma unroll
        for (int st = 0; st < 2; st++) {
            #pragma unroll
            for (int i = 0; i < 2; i++) {
                cp_async16(&Ks[st * FTILE + lr * QLD + lc + i * 8],
                           &kb[(size_t)(st * 64 + lr) * Dd + lc + i * 8]);
                cp_async16(&Vs[st * FTILE + lr * QLD + lc + i * 8],
                           &vb[(size_t)(st * 64 + lr) * Dd + lc + i * 8]);
            }
            cp_commit();
        }
    }

    const uint32_t qs_b = (uint32_t)__cvta_generic_to_shared(Qs);
    const uint32_t ks_b = (uint32_t)__cvta_generic_to_shared(Ks);
    const uint32_t vs_b = (uint32_t)__cvta_generic_to_shared(Vs);

    cp_wait<1>();
    __syncthreads();

    uint32_t qa[4][4];
    {
        int r = w * 16 + (lane & 15);
        int cbase = 8 * (lane >> 4);
        #pragma unroll
        for (int kk = 0; kk < 4; kk++)
            ldsm_x4(qa[kk], qs_b + (uint32_t)(r * QLD + kk * 16 + cbase) * 2);
    }

    float oacc[8][4];
    #pragma unroll
    for (int i = 0; i < 8; i++)
        #pragma unroll
        for (int j = 0; j < 4; j++) oacc[i][j] = 0.f;
    float l0 = 0.f, l1 = 0.f;

    const int colb  = 2 * (lane & 3);
    const int row0g = qt * 128 + w * 16 + (lane >> 2);

    const int kK_row = (lane & 7) + 8 * (lane >> 4);
    const int kK_col = 8 * ((lane >> 3) & 1);
    const int vV_row = (lane & 7) + 8 * ((lane >> 3) & 1);
    const int vV_col = 8 * (lane >> 4);

    const int NT = SEQ / 64;
    int sidx = 0;
    for (int t = 0; t < NT; t++) {
        const int kt = t * 64;
        if (t < NT - 1) cp_wait<1>(); else cp_wait<0>();
        __syncthreads();

        if (t + 2 < NT) {
            const int st = (sidx + 2 >= 3) ? sidx - 1 : sidx + 2;
            const int kn = kt + 128;
            __half* Kd = &Ks[st * FTILE];
            __half* Vd = &Vs[st * FTILE];
            int lr = tid >> 2, lc = (tid & 3) * 16;
            #pragma unroll
            for (int i = 0; i < 2; i++) {
                cp_async16(&Kd[lr * QLD + lc + i * 8], &kb[(size_t)(kn + lr) * Dd + lc + i * 8]);
                cp_async16(&Vd[lr * QLD + lc + i * 8], &vb[(size_t)(kn + lr) * Dd + lc + i * 8]);
            }
            cp_commit();
        }

        const uint32_t ks_s = ks_b + (uint32_t)(sidx * FTILE) * 2;
        const uint32_t vs_s = vs_b + (uint32_t)(sidx * FTILE) * 2;

        float sfr[8][4];
        #pragma unroll
        for (int i = 0; i < 8; i++)
            #pragma unroll
            for (int j = 0; j < 4; j++) sfr[i][j] = 0.f;

        #pragma unroll
        for (int kk = 0; kk < 4; kk++) {
            const int d0 = kk * 16;
            #pragma unroll
            for (int np = 0; np < 4; np++) {
                uint32_t kr[4];
                ldsm_x4(kr, ks_s + (uint32_t)((np * 16 + kK_row) * QLD + d0 + kK_col) * 2);
                mma16816(sfr[2 * np],     qa[kk], kr);
                mma16816(sfr[2 * np + 1], qa[kk], kr + 2);
            }
        }

        #pragma unroll
        for (int kk = 0; kk < 4; kk++) {
            uint32_t pa[4];
            #pragma unroll
            for (int half16 = 0; half16 < 2; half16++) {
                const int nt = kk * 2 + half16;
                int col = kt + nt * 8 + colb;
                float p0 = ex2f(sfr[nt][0] + ((col    ) <= row0g     ? C_IN : C_OUT));
                float p1 = ex2f(sfr[nt][1] + ((col + 1) <= row0g     ? C_IN : C_OUT));
                float p2 = ex2f(sfr[nt][2] + ((col    ) <= row0g + 8 ? C_IN : C_OUT));
                float p3 = ex2f(sfr[nt][3] + ((col + 1) <= row0g + 8 ? C_IN : C_OUT));
                l0 += p0 + p1;
                l1 += p2 + p3;
                pa[half16 * 2]     = packh2(p0, p1);
                pa[half16 * 2 + 1] = packh2(p2, p3);
            }
            const int k0 = kk * 16;
            #pragma unroll
            for (int dp = 0; dp < 4; dp++) {
                uint32_t vr[4];
                ldsm_x4_t(vr, vs_s + (uint32_t)((k0 + vV_row) * QLD + dp * 16 + vV_col) * 2);
                mma16816(oacc[2 * dp],     pa, vr);
                mma16816(oacc[2 * dp + 1], pa, vr + 2);
            }
        }
        sidx = (sidx + 1 >= 3) ? 0 : sidx + 1;
    }

    l0 += __shfl_xor_sync(0xffffffffu, l0, 1);
    l0 += __shfl_xor_sync(0xffffffffu, l0, 2);
    l1 += __shfl_xor_sync(0xffffffffu, l1, 1);
    l1 += __shfl_xor_sync(0xffffffffu, l1, 2);
    const float invl0 = 1.f / l0, invl1 = 1.f / l1;

    const int b = bh >> 4, h = bh & 15;
    const int r0 = qt * 128 + w * 16 + (lane >> 2);
    __half* d0p = out + ((size_t)(b * SEQ + r0    )) * Hh + h * Dd;
    __half* d1p = out + ((size_t)(b * SEQ + r0 + 8)) * Hh + h * Dd;
    #pragma unroll
    for (int nt = 0; nt < 8; nt++) {
        int col = nt * 8 + colb;
        *(__half2*)&d0p[col] = __floats2half2_rn(oacc[nt][0] * invl0, oacc[nt][1] * invl0);
        *(__half2*)&d1p[col] = __floats2half2_rn(oacc[nt][2] * invl1, oacc[nt][3] * invl1);
    }
}

// ---------------------------------------------------------------------------
extern "C" void kernel_launch(void* const* d_in, const int* in_sizes, int n_in,
                              void* d_out, int out_size)
{
    const float* hs   = (const float*)d_in[0];
    const float* cosT = (const float*)d_in[1];
    const float* sinT = (const float*)d_in[2];
    const float* Wq   = (const float*)d_in[3];
    const float* bq   = (const float*)d_in[4];
    const float* Wk   = (const float*)d_in[5];
    const float* bk   = (const float*)d_in[6];
    const float* Wv   = (const float*)d_in[7];
    const float* bv   = (const float*)d_in[8];
    const float* Wo   = (const float*)d_in[9];
    const float* bo   = (const float*)d_in[10];
    const float* rw   = (const float*)d_in[11];
    float* out = (float*)d_out;

    float* f32 = nullptr;  cudaGetSymbolAddress((void**)&f32, g_f32);
    __half* f16 = nullptr; cudaGetSymbolAddress((void**)&f16, g_f16);

    const size_t SZ = SZc;
    const size_t WZ = WZc;
    __half* qlinH = (__half*)f32;
    __half* klinH = qlinH + SZ;
    __half* vlinH = klinH + SZ;

    __half* hs_h  = f16;
    __half* Wq_h  = f16 + SZ;
    __half* Wk_h  = Wq_h + WZ;
    __half* Wv_h  = Wk_h + WZ;
    __half* Wo_h  = Wv_h + WZ;
    __half* qT    = Wo_h + WZ;
    __half* kT    = qT + SZ;
    __half* vT    = kT + SZ;
    __half* attn  = vT + SZ;

    cudaFuncSetAttribute(flash_mma_kernel,
                         cudaFuncAttributeMaxDynamicSharedMemorySize, FSM_BYTES);
    cudaFuncSetAttribute(gemm_mma_kernel,
                         cudaFuncAttributeMaxDynamicSharedMemorySize, GEMM_SMEM);

    // 8M elems, 8 per thread
    f2h_all_kernel<<<(int)((SZ + 4 * WZ) / 2048), 256>>>(hs, Wq, Wk, Wv, Wo, f16);

    dim3 gqkv(Hh / 128, Mtok / 128, 3);
    gemm_mma_kernel<<<gqkv, 256, GEMM_SMEM>>>(hs_h, Wq_h, Wk_h, Wv_h,
                                              qlinH, klinH, vlinH,
                                              nullptr, nullptr);

    normrope_kernel<<<Mtok, 256>>>(qlinH, klinH, vlinH, bq, bk, bv,
                                   cosT, sinT, rw, qT, kT, vT);

    dim3 fg(SEQ / 128, Bb * NHd);
    flash_mma_kernel<<<fg, 256, FSM_BYTES>>>(qT, kT, vT, attn);

    dim3 gout(Hh / 128, Mtok / 128, 1);
    gemm_mma_kernel<<<gout, 256, GEMM_SMEM>>>(attn, Wo_h, Wo_h, Wo_h,
                                              nullptr, nullptr, nullptr,
                                              out, bo);
}

// round 17
// speedup vs baseline: 1.1516x; 1.0159x over previous
#include <cuda_runtime.h>
#include <cuda_fp16.h>
#include <math.h>
#include <stdint.h>

#define Bb    2
#define SEQ   2048
#define Hh    1024
#define NHd   16
#define Dd    64
#define Mtok  4096

__device__ float  g_f32[(size_t)3 * Mtok * Hh];   // reused as half qlin/klin/vlin
__device__ __half g_f16[(size_t)(4 + 4 + 12 + 4) * 1024 * 1024];

__device__ __forceinline__ void cp_async16(void* smem, const void* gmem) {
    unsigned saddr = (unsigned)__cvta_generic_to_shared(smem);
    asm volatile("cp.async.cg.shared.global [%0], [%1], 16;\n" :: "r"(saddr), "l"(gmem));
}
__device__ __forceinline__ void cp_commit() { asm volatile("cp.async.commit_group;\n"); }
template <int N>
__device__ __forceinline__ void cp_wait() { asm volatile("cp.async.wait_group %0;\n" :: "n"(N)); }

__device__ __forceinline__ void ldsm_x4(uint32_t* r, uint32_t saddr) {
    asm volatile("ldmatrix.sync.aligned.m8n8.x4.shared.b16 {%0,%1,%2,%3}, [%4];"
                 : "=r"(r[0]), "=r"(r[1]), "=r"(r[2]), "=r"(r[3]) : "r"(saddr));
}
__device__ __forceinline__ void ldsm_x4_t(uint32_t* r, uint32_t saddr) {
    asm volatile("ldmatrix.sync.aligned.m8n8.x4.trans.shared.b16 {%0,%1,%2,%3}, [%4];"
                 : "=r"(r[0]), "=r"(r[1]), "=r"(r[2]), "=r"(r[3]) : "r"(saddr));
}
__device__ __forceinline__ void mma16816(float* c, const uint32_t* a, const uint32_t* b) {
    asm volatile(
        "mma.sync.aligned.m16n8k16.row.col.f32.f16.f16.f32 "
        "{%0,%1,%2,%3}, {%4,%5,%6,%7}, {%8,%9}, {%0,%1,%2,%3};"
        : "+f"(c[0]), "+f"(c[1]), "+f"(c[2]), "+f"(c[3])
        : "r"(a[0]), "r"(a[1]), "r"(a[2]), "r"(a[3]), "r"(b[0]), "r"(b[1]));
}
__device__ __forceinline__ uint32_t packh2(float x, float y) {
    __half2 h = __floats2half2_rn(x, y);
    return *(uint32_t*)&h;
}
__device__ __forceinline__ float ex2f(float x) {
    float y; asm("ex2.approx.f32 %0, %1;" : "=f"(y) : "f"(x)); return y;
}
__device__ __forceinline__ void grid_dep_sync() {
#if __CUDA_ARCH__ >= 900
    cudaGridDependencySynchronize();
#endif
}

// ---------------------------------------------------------------------------
// fused fp32->fp16 conversion: 8 elems/thread
// ---------------------------------------------------------------------------
#define SZc ((size_t)Mtok * Hh)
#define WZc ((size_t)Hh * Hh)
__global__ __launch_bounds__(256)
void f2h_all_kernel(const float* __restrict__ hs,
                    const float* __restrict__ Wq, const float* __restrict__ Wk,
                    const float* __restrict__ Wv, const float* __restrict__ Wo,
                    __half* __restrict__ dst)
{
    size_t i8 = ((size_t)blockIdx.x * 256 + threadIdx.x) * 8;
    const float* s;
    if (i8 < SZc) s = &hs[i8];
    else {
        size_t wo = i8 - SZc;
        s = (wo < WZc)     ? &Wq[wo]
          : (wo < 2 * WZc) ? &Wk[wo - WZc]
          : (wo < 3 * WZc) ? &Wv[wo - 2 * WZc]
                           : &Wo[wo - 3 * WZc];
    }
    float4 v0 = *(const float4*)s;
    float4 v1 = *(const float4*)(s + 4);
    __half2 h[4];
    h[0] = __floats2half2_rn(v0.x, v0.y);
    h[1] = __floats2half2_rn(v0.z, v0.w);
    h[2] = __floats2half2_rn(v1.x, v1.y);
    h[3] = __floats2half2_rn(v1.z, v1.w);
    *(float4*)&dst[i8] = *(float4*)h;
}

// ---------------------------------------------------------------------------
// Raw-mma fp16 GEMM: 128x128 CTA tile, 8 warps x (32x64), BK=32,
// 4-stage cp.async (wait<2>), register epilogue. PDL consumer.
// ---------------------------------------------------------------------------
#define GBK  32
#define GLDG 40
#define GSTG (128 * GLDG)
#define GNS  4
#define GEMM_SMEM (2 * GNS * GSTG * 2)   // 81920
#define NITER 32

__global__ __launch_bounds__(256, 2)
void gemm_mma_kernel(const __half* __restrict__ A,
                     const __half* __restrict__ W0, const __half* __restrict__ W1,
                     const __half* __restrict__ W2,
                     __half* __restrict__ H0, __half* __restrict__ H1,
                     __half* __restrict__ H2,
                     float* __restrict__ F, const float* __restrict__ bias)
{
    extern __shared__ __align__(16) __half gsm[];
    __half* As = gsm;                    // [4][GSTG]
    __half* Bs = gsm + GNS * GSTG;       // [4][GSTG]

    const __half* W = (blockIdx.z == 0) ? W0 : (blockIdx.z == 1) ? W1 : W2;
    __half*       H = (blockIdx.z == 0) ? H0 : (blockIdx.z == 1) ? H1 : H2;

    const int tid  = threadIdx.x;
    const int w    = tid >> 5;
    const int lane = tid & 31;
    const int wr = w & 3;
    const int wc = w >> 2;
    const int bm = blockIdx.y * 128, bn = blockIdx.x * 128;
    const int K = 1024;

    float acc[2][8][4];
    #pragma unroll
    for (int m = 0; m < 2; m++)
        #pragma unroll
        for (int n = 0; n < 8; n++)
            #pragma unroll
            for (int j = 0; j < 4; j++) acc[m][n][j] = 0.f;

    const int lr = tid >> 2;
    const int lc = (tid & 3) * 8;

    grid_dep_sync();   // wait for producer kernel before reading its output

    // prefetch stages 0..2
    #pragma unroll
    for (int st = 0; st < 3; st++) {
        const int k0 = st * GBK;
        #pragma unroll
        for (int i = 0; i < 2; i++) {
            int r = lr + i * 64;
            cp_async16(&As[st * GSTG + r * GLDG + lc], &A[(size_t)(bm + r) * K + k0 + lc]);
            cp_async16(&Bs[st * GSTG + r * GLDG + lc], &W[(size_t)(bn + r) * K + k0 + lc]);
        }
        cp_commit();
    }

    const uint32_t as_b = (uint32_t)__cvta_generic_to_shared(As);
    const uint32_t bs_b = (uint32_t)__cvta_generic_to_shared(Bs);

    const int aA_row = wr * 32 + (lane & 15);
    const int aA_col = 8 * (lane >> 4);
    const int bB_row = wc * 64 + (lane & 7) + 8 * (lane >> 4);
    const int bB_col = 8 * ((lane >> 3) & 1);

    int sidx = 0;
    for (int it = 0; it < NITER; it++) {
        if (it < NITER - 2)      cp_wait<2>();
        else if (it < NITER - 1) cp_wait<1>();
        else                     cp_wait<0>();
        __syncthreads();

        if (it + 3 < NITER) {
            const int st = (sidx + 3) & 3;
            const int k0 = (it + 3) * GBK;
            #pragma unroll
            for (int i = 0; i < 2; i++) {
                int r = lr + i * 64;
                cp_async16(&As[st * GSTG + r * GLDG + lc], &A[(size_t)(bm + r) * K + k0 + lc]);
                cp_async16(&Bs[st * GSTG + r * GLDG + lc], &W[(size_t)(bn + r) * K + k0 + lc]);
            }
            cp_commit();
        }

        const uint32_t as_s = as_b + (uint32_t)(sidx * GSTG) * 2;
        const uint32_t bs_s = bs_b + (uint32_t)(sidx * GSTG) * 2;

        #pragma unroll
        for (int kk = 0; kk < 2; kk++) {
            const int kd = kk * 16;
            uint32_t af[2][4];
            #pragma unroll
            for (int m = 0; m < 2; m++)
                ldsm_x4(af[m], as_s + (uint32_t)((aA_row + m * 16) * GLDG + kd + aA_col) * 2);
            #pragma unroll
            for (int np = 0; np < 4; np++) {
                uint32_t bf[4];
                ldsm_x4(bf, bs_s + (uint32_t)((bB_row + np * 16) * GLDG + kd + bB_col) * 2);
                mma16816(acc[0][np * 2],     af[0], bf);
                mma16816(acc[0][np * 2 + 1], af[0], bf + 2);
                mma16816(acc[1][np * 2],     af[1], bf);
                mma16816(acc[1][np * 2 + 1], af[1], bf + 2);
            }
        }
        sidx = (sidx + 1) & 3;
    }

    const int colb = 2 * (lane & 3);
    if (H != nullptr) {
        #pragma unroll
        for (int m = 0; m < 2; m++) {
            const int r0 = bm + wr * 32 + m * 16 + (lane >> 2);
            __half* p0 = &H[(size_t)r0 * 1024 + bn + wc * 64];
            __half* p1 = &H[(size_t)(r0 + 8) * 1024 + bn + wc * 64];
            #pragma unroll
            for (int n = 0; n < 8; n++) {
                *(uint32_t*)&p0[n * 8 + colb] = packh2(acc[m][n][0], acc[m][n][1]);
                *(uint32_t*)&p1[n * 8 + colb] = packh2(acc[m][n][2], acc[m][n][3]);
            }
        }
    } else {
        #pragma unroll
        for (int m = 0; m < 2; m++) {
            const int r0 = bm + wr * 32 + m * 16 + (lane >> 2);
            float* p0 = &F[(size_t)r0 * 1024 + bn + wc * 64];
            float* p1 = &F[(size_t)(r0 + 8) * 1024 + bn + wc * 64];
            const float* bp = &bias[bn + wc * 64];
            #pragma unroll
            for (int n = 0; n < 8; n++) {
                float b0 = bp[n * 8 + colb], b1 = bp[n * 8 + colb + 1];
                float2 o0 = { acc[m][n][0] + b0, acc[m][n][1] + b1 };
                float2 o1 = { acc[m][n][2] + b0, acc[m][n][3] + b1 };
                *(float2*)&p0[n * 8 + colb] = o0;
                *(float2*)&p1[n * 8 + colb] = o1;
            }
        }
    }
}

// ---------------------------------------------------------------------------
// RMSNorm + bias + RoPE: 1 token/block, 4 contiguous elems/thread,
// float4 loads of biases/cos/sin/w. PDL consumer.
// ---------------------------------------------------------------------------
#define QSCALE (0.125f * 1.44269504089f)

__global__ __launch_bounds__(256)
void normrope_kernel(const __half* __restrict__ qlin, const __half* __restrict__ klin,
                     const __half* __restrict__ vlin,
                     const float* __restrict__ bq, const float* __restrict__ bk,
                     const float* __restrict__ bv,
                     const float* __restrict__ cosT, const float* __restrict__ sinT,
                     const float* __restrict__ w,
                     __half* __restrict__ qo, __half* __restrict__ ko, __half* __restrict__ vo)
{
    const int t = blockIdx.x;
    const int b = t >> 11;
    const int s = t & 2047;
    const int tid = threadIdx.x;
    const int i0 = tid * 4;

    __shared__ float sq[1024], sk[1024];
    __shared__ float red[16];
    __shared__ float rqs, rks;

    grid_dep_sync();

    float sumq = 0.f, sumk = 0.f;
    {
        __half2 q01 = *(const __half2*)&qlin[(size_t)t * 1024 + i0];
        __half2 q23 = *(const __half2*)&qlin[(size_t)t * 1024 + i0 + 2];
        __half2 k01 = *(const __half2*)&klin[(size_t)t * 1024 + i0];
        __half2 k23 = *(const __half2*)&klin[(size_t)t * 1024 + i0 + 2];
        float4 bq4 = *(const float4*)&bq[i0];
        float4 bk4 = *(const float4*)&bk[i0];
        float x0 = __half2float(q01.x) + bq4.x, x1 = __half2float(q01.y) + bq4.y;
        float x2 = __half2float(q23.x) + bq4.z, x3 = __half2float(q23.y) + bq4.w;
        float y0 = __half2float(k01.x) + bk4.x, y1 = __half2float(k01.y) + bk4.y;
        float y2 = __half2float(k23.x) + bk4.z, y3 = __half2float(k23.y) + bk4.w;
        sq[i0] = x0; sq[i0 + 1] = x1; sq[i0 + 2] = x2; sq[i0 + 3] = x3;
        sk[i0] = y0; sk[i0 + 1] = y1; sk[i0 + 2] = y2; sk[i0 + 3] = y3;
        sumq = (x0 * x0 + x1 * x1) + (x2 * x2 + x3 * x3);
        sumk = (y0 * y0 + y1 * y1) + (y2 * y2 + y3 * y3);
    }
    #pragma unroll
    for (int off = 16; off > 0; off >>= 1) {
        sumq += __shfl_down_sync(0xffffffffu, sumq, off);
        sumk += __shfl_down_sync(0xffffffffu, sumk, off);
    }
    if ((tid & 31) == 0) { red[tid >> 5] = sumq; red[8 + (tid >> 5)] = sumk; }
    __syncthreads();
    if (tid == 0) {
        float a = 0.f, c = 0.f;
        #pragma unroll
        for (int i2 = 0; i2 < 8; i2++) { a += red[i2]; c += red[8 + i2]; }
        rqs = rsqrtf(a * (1.0f / 1024.0f) + 1e-6f);
        rks = rsqrtf(c * (1.0f / 1024.0f) + 1e-6f);
    }
    __syncthreads();
    const float rq = rqs, rk = rks;

    {
        const int h = i0 >> 6, d = i0 & 63;
        const int pbase = (d < 32) ? i0 + 32 : i0 - 32;
        const float sign = (d < 32) ? -1.f : 1.f;
        float4 cs4 = *(const float4*)&cosT[s * 64 + d];
        float4 sn4 = *(const float4*)&sinT[s * 64 + d];
        float4 w4  = *(const float4*)&w[i0];
        float4 wp4 = *(const float4*)&w[pbase];
        float qv[4], kv[4];
        #pragma unroll
        for (int j = 0; j < 4; j++) {
            float wv = (&w4.x)[j], wp = (&wp4.x)[j];
            float cs = (&cs4.x)[j], sn = (&sn4.x)[j];
            float qx = sq[i0 + j] * rq * wv, qp = sq[pbase + j] * rq * wp;
            float kx = sk[i0 + j] * rk * wv, kp = sk[pbase + j] * rk * wp;
            qv[j] = (qx * cs + sign * qp * sn) * QSCALE;
            kv[j] = kx * cs + sign * kp * sn;
        }
        size_t oidx = ((size_t)(b * NHd + h) * SEQ + s) * Dd + d;
        *(__half2*)&qo[oidx]     = __floats2half2_rn(qv[0], qv[1]);
        *(__half2*)&qo[oidx + 2] = __floats2half2_rn(qv[2], qv[3]);
        *(__half2*)&ko[oidx]     = __floats2half2_rn(kv[0], kv[1]);
        *(__half2*)&ko[oidx + 2] = __floats2half2_rn(kv[2], kv[3]);
        __half2 v01 = *(const __half2*)&vlin[(size_t)t * 1024 + i0];
        __half2 v23 = *(const __half2*)&vlin[(size_t)t * 1024 + i0 + 2];
        float4 bv4 = *(const float4*)&bv[i0];
        *(__half2*)&vo[oidx]     = __floats2half2_rn(__half2float(v01.x) + bv4.x,
                                                     __half2float(v01.y) + bv4.y);
        *(__half2*)&vo[oidx + 2] = __floats2half2_rn(__half2float(v23.x) + bv4.z,
                                                     __half2float(v23.y) + bv4.w);
    }
}

// ---------------------------------------------------------------------------
// Flash attention (best measured config): raw mma.sync, 8 warps x 16 q-rows,
// register S/P, exp2-domain scores, 3-stage K/V ring. PDL consumer.
// ---------------------------------------------------------------------------
#define QLD 72
#define FTILE (64 * QLD)
#define FSM_BYTES ((128 * QLD + 6 * FTILE) * 2)    // 73728
#define C_IN  (-2.88539008178f)
#define C_OUT (-4.32808512267f)

__global__ __launch_bounds__(256, 2)
void flash_mma_kernel(const __half* __restrict__ q, const __half* __restrict__ k,
                      const __half* __restrict__ v, __half* __restrict__ out)
{
    extern __shared__ __align__(16) char smraw[];
    __half* Qs = (__half*)smraw;               // [128][QLD]
    __half* Ks = Qs + 128 * QLD;               // [3][64][QLD]
    __half* Vs = Ks + 3 * FTILE;               // [3][64][QLD]

    const int tid  = threadIdx.x;
    const int w    = tid >> 5;
    const int lane = tid & 31;
    const int bh   = blockIdx.y;
    const int qt   = blockIdx.x;
    const __half* kb = k + (size_t)bh * SEQ * Dd;
    const __half* vb = v + (size_t)bh * SEQ * Dd;
    const __half* qb = q + ((size_t)bh * SEQ + qt * 128) * Dd;

    grid_dep_sync();

    {
        int r = tid >> 1, c0 = (tid & 1) * 32;
        #pragma unroll
        for (int i = 0; i < 4; i++)
            cp_async16(&Qs[r * QLD + c0 + i * 8], &qb[(size_t)r * Dd + c0 + i * 8]);
        int lr = tid >> 2, lc = (tid & 3) * 16;
        #pragma unroll
        for (int st = 0; st < 2; st++) {
            #pragma unroll
            for (int i = 0; i < 2; i++) {
                cp_async16(&Ks[st * FTILE + lr * QLD + lc + i * 8],
                           &kb[(size_t)(st * 64 + lr) * Dd + lc + i * 8]);
                cp_async16(&Vs[st * FTILE + lr * QLD + lc + i * 8],
                           &vb[(size_t)(st * 64 + lr) * Dd + lc + i * 8]);
            }
            cp_commit();
        }
    }

    const uint32_t qs_b = (uint32_t)__cvta_generic_to_shared(Qs);
    const uint32_t ks_b = (uint32_t)__cvta_generic_to_shared(Ks);
    const uint32_t vs_b = (uint32_t)__cvta_generic_to_shared(Vs);

    cp_wait<1>();
    __syncthreads();

    uint32_t qa[4][4];
    {
        int r = w * 16 + (lane & 15);
        int cbase = 8 * (lane >> 4);
        #pragma unroll
        for (int kk = 0; kk < 4; kk++)
            ldsm_x4(qa[kk], qs_b + (uint32_t)(r * QLD + kk * 16 + cbase) * 2);
    }

    float oacc[8][4];
    #pragma unroll
    for (int i = 0; i < 8; i++)
        #pragma unroll
        for (int j = 0; j < 4; j++) oacc[i][j] = 0.f;
    float l0 = 0.f, l1 = 0.f;

    const int colb  = 2 * (lane & 3);
    const int row0g = qt * 128 + w * 16 + (lane >> 2);

    const int kK_row = (lane & 7) + 8 * (lane >> 4);
    const int kK_col = 8 * ((lane >> 3) & 1);
    const int vV_row = (lane & 7) + 8 * ((lane >> 3) & 1);
    const int vV_col = 8 * (lane >> 4);

    const int NT = SEQ / 64;
    int sidx = 0;
    for (int t = 0; t < NT; t++) {
        const int kt = t * 64;
        if (t < NT - 1) cp_wait<1>(); else cp_wait<0>();
        __syncthreads();

        if (t + 2 < NT) {
            const int st = (sidx + 2 >= 3) ? sidx - 1 : sidx + 2;
            const int kn = kt + 128;
            __half* Kd = &Ks[st * FTILE];
            __half* Vd = &Vs[st * FTILE];
            int lr = tid >> 2, lc = (tid & 3) * 16;
            #pragma unroll
            for (int i = 0; i < 2; i++) {
                cp_async16(&Kd[lr * QLD + lc + i * 8], &kb[(size_t)(kn + lr) * Dd + lc + i * 8]);
                cp_async16(&Vd[lr * QLD + lc + i * 8], &vb[(size_t)(kn + lr) * Dd + lc + i * 8]);
            }
            cp_commit();
        }

        const uint32_t ks_s = ks_b + (uint32_t)(sidx * FTILE) * 2;
        const uint32_t vs_s = vs_b + (uint32_t)(sidx * FTILE) * 2;

        float sfr[8][4];
        #pragma unroll
        for (int i = 0; i < 8; i++)
            #pragma unroll
            for (int j = 0; j < 4; j++) sfr[i][j] = 0.f;

        #pragma unroll
        for (int kk = 0; kk < 4; kk++) {
            const int d0 = kk * 16;
            #pragma unroll
            for (int np = 0; np < 4; np++) {
                uint32_t kr[4];
                ldsm_x4(kr, ks_s + (uint32_t)((np * 16 + kK_row) * QLD + d0 + kK_col) * 2);
                mma16816(sfr[2 * np],     qa[kk], kr);
                mma16816(sfr[2 * np + 1], qa[kk], kr + 2);
            }
        }

        #pragma unroll
        for (int kk = 0; kk < 4; kk++) {
            uint32_t pa[4];
            #pragma unroll
            for (int half16 = 0; half16 < 2; half16++) {
                const int nt = kk * 2 + half16;
                int col = kt + nt * 8 + colb;
                float p0 = ex2f(sfr[nt][0] + ((col    ) <= row0g     ? C_IN : C_OUT));
                float p1 = ex2f(sfr[nt][1] + ((col + 1) <= row0g     ? C_IN : C_OUT));
                float p2 = ex2f(sfr[nt][2] + ((col    ) <= row0g + 8 ? C_IN : C_OUT));
                float p3 = ex2f(sfr[nt][3] + ((col + 1) <= row0g + 8 ? C_IN : C_OUT));
                l0 += p0 + p1;
                l1 += p2 + p3;
                pa[half16 * 2]     = packh2(p0, p1);
                pa[half16 * 2 + 1] = packh2(p2, p3);
            }
            const int k0 = kk * 16;
            #pragma unroll
            for (int dp = 0; dp < 4; dp++) {
                uint32_t vr[4];
                ldsm_x4_t(vr, vs_s + (uint32_t)((k0 + vV_row) * QLD + dp * 16 + vV_col) * 2);
                mma16816(oacc[2 * dp],     pa, vr);
                mma16816(oacc[2 * dp + 1], pa, vr + 2);
            }
        }
        sidx = (sidx + 1 >= 3) ? 0 : sidx + 1;
    }

    l0 += __shfl_xor_sync(0xffffffffu, l0, 1);
    l0 += __shfl_xor_sync(0xffffffffu, l0, 2);
    l1 += __shfl_xor_sync(0xffffffffu, l1, 1);
    l1 += __shfl_xor_sync(0xffffffffu, l1, 2);
    const float invl0 = 1.f / l0, invl1 = 1.f / l1;

    const int b = bh >> 4, h = bh & 15;
    const int r0 = qt * 128 + w * 16 + (lane >> 2);
    __half* d0p = out + ((size_t)(b * SEQ + r0    )) * Hh + h * Dd;
    __half* d1p = out + ((size_t)(b * SEQ + r0 + 8)) * Hh + h * Dd;
    #pragma unroll
    for (int nt = 0; nt < 8; nt++) {
        int col = nt * 8 + colb;
        *(__half2*)&d0p[col] = __floats2half2_rn(oacc[nt][0] * invl0, oacc[nt][1] * invl0);
        *(__half2*)&d1p[col] = __floats2half2_rn(oacc[nt][2] * invl1, oacc[nt][3] * invl1);
    }
}

// ---------------------------------------------------------------------------
// host-side PDL launch helper
// ---------------------------------------------------------------------------
template <typename... Args>
static void launch_pdl(void (*kern)(Args...), dim3 grid, dim3 block,
                       size_t smem, Args... args)
{
    cudaLaunchConfig_t cfg = {};
    cfg.gridDim = grid;
    cfg.blockDim = block;
    cfg.dynamicSmemBytes = smem;
    cudaLaunchAttribute attr[1];
    attr[0].id = cudaLaunchAttributeProgrammaticStreamSerialization;
    attr[0].val.programmaticStreamSerializationAllowed = 1;
    cfg.attrs = attr;
    cfg.numAttrs = 1;
    cudaLaunchKernelEx(&cfg, kern, args...);
}

// ---------------------------------------------------------------------------
extern "C" void kernel_launch(void* const* d_in, const int* in_sizes, int n_in,
                              void* d_out, int out_size)
{
    const float* hs   = (const float*)d_in[0];
    const float* cosT = (const float*)d_in[1];
    const float* sinT = (const float*)d_in[2];
    const float* Wq   = (const float*)d_in[3];
    const float* bq   = (const float*)d_in[4];
    const float* Wk   = (const float*)d_in[5];
    const float* bk   = (const float*)d_in[6];
    const float* Wv   = (const float*)d_in[7];
    const float* bv   = (const float*)d_in[8];
    const float* Wo   = (const float*)d_in[9];
    const float* bo   = (const float*)d_in[10];
    const float* rw   = (const float*)d_in[11];
    float* out = (float*)d_out;

    float* f32 = nullptr;  cudaGetSymbolAddress((void**)&f32, g_f32);
    __half* f16 = nullptr; cudaGetSymbolAddress((void**)&f16, g_f16);

    const size_t SZ = SZc;
    const size_t WZ = WZc;
    __half* qlinH = (__half*)f32;
    __half* klinH = qlinH + SZ;
    __half* vlinH = klinH + SZ;

    __half* hs_h  = f16;
    __half* Wq_h  = f16 + SZ;
    __half* Wk_h  = Wq_h + WZ;
    __half* Wv_h  = Wk_h + WZ;
    __half* Wo_h  = Wv_h + WZ;
    __half* qT    = Wo_h + WZ;
    __half* kT    = qT + SZ;
    __half* vT    = kT + SZ;
    __half* attn  = vT + SZ;

    cudaFuncSetAttribute(flash_mma_kernel,
                         cudaFuncAttributeMaxDynamicSharedMemorySize, FSM_BYTES);
    cudaFuncSetAttribute(gemm_mma_kernel,
                         cudaFuncAttributeMaxDynamicSharedMemorySize, GEMM_SMEM);

    f2h_all_kernel<<<(int)((SZ + 4 * WZ) / 2048), 256>>>(hs, Wq, Wk, Wv, Wo, f16);

    dim3 gqkv(Hh / 128, Mtok / 128, 3);
    launch_pdl(gemm_mma_kernel, gqkv, dim3(256), (size_t)GEMM_SMEM,
               (const __half*)hs_h, (const __half*)Wq_h, (const __half*)Wk_h,
               (const __half*)Wv_h, qlinH, klinH, vlinH,
               (float*)nullptr, (const float*)nullptr);

    launch_pdl(normrope_kernel, dim3(Mtok), dim3(256), (size_t)0,
               (const __half*)qlinH, (const __half*)klinH, (const __half*)vlinH,
               bq, bk, bv, cosT, sinT, rw, qT, kT, vT);

    dim3 fg(SEQ / 128, Bb * NHd);
    launch_pdl(flash_mma_kernel, fg, dim3(256), (size_t)FSM_BYTES,
               (const __half*)qT, (const __half*)kT, (const __half*)vT, attn);

    dim3 gout(Hh / 128, Mtok / 128, 1);
    launch_pdl(gemm_mma_kernel, gout, dim3(256), (size_t)GEMM_SMEM,
               (const __half*)attn, (const __half*)Wo_h, (const __half*)Wo_h,
               (const __half*)Wo_h, (__half*)nullptr, (__half*)nullptr,
               (__half*)nullptr, out, bo);
}